// round 14
// baseline (speedup 1.0000x reference)
#include <cuda_runtime.h>
#include <cuda_bf16.h>

#define NB 32
#define LEPS 5.9604645e-8f
#define LUNFL 1.1754944e-38f

__device__ float g_P2[NB][2][12];
__device__ float g_Kn[NB][4];
__device__ int   g_scores[NB][4];
__device__ int   g_counts[NB];

__device__ __forceinline__ float fsign(float a, float b){ return copysignf(a,b); }
__device__ __forceinline__ float fdiv(float a, float b){ return __fdividef(a,b); }
__device__ __forceinline__ float fsqrt(float x){ return (x<=0.f)?0.f:x*rsqrtf(x); }

// division-free slartg: one MUFU.RSQ, outputs independent off rs
__device__ __forceinline__ void slartg(float f,float g,float*cs,float*sn,float*r){
    if(g==0.f){ *cs=1.f; *sn=0.f; *r=f; }
    else if(f==0.f){ *cs=0.f; *sn=fsign(1.f,g); *r=fabsf(g); }
    else{
        float s2=fmaf(f,f,g*g);
        float rs=rsqrtf(s2);
        float d=s2*rs;
        *cs=fabsf(f)*rs;
        *r=fsign(d,f);
        *sn=g*rs*fsign(1.f,f);
    }
}

__device__ void slas2(float f,float g,float h,float*ssmin,float*ssmax){
    float fa=fabsf(f), ga=fabsf(g), ha=fabsf(h);
    float fhmn=fminf(fa,ha), fhmx=fmaxf(fa,ha);
    if(fhmn==0.f){
        *ssmin=0.f;
        if(fhmx==0.f) *ssmax=ga;
        else{ float mn=fminf(fhmx,ga), mx=fmaxf(fhmx,ga);
              float q=fdiv(mn,mx); *ssmax=mx*fsqrt(1.f+q*q); }
    }else if(ga<fhmx){
        float as=1.f+fdiv(fhmn,fhmx), at=fdiv(fhmx-fhmn,fhmx), au=fdiv(ga,fhmx)*fdiv(ga,fhmx);
        float c=fdiv(2.f,fsqrt(as*as+au)+fsqrt(at*at+au));
        *ssmin=fhmn*c; *ssmax=fdiv(fhmx,c);
    }else{
        float au=fdiv(fhmx,ga);
        if(au==0.f){ *ssmin=fdiv(fhmn*fhmx,ga); *ssmax=ga; }
        else{
            float as=1.f+fdiv(fhmn,fhmx), at=fdiv(fhmx-fhmn,fhmx);
            float c=fdiv(1.f,fsqrt(1.f+(as*au)*(as*au))+fsqrt(1.f+(at*au)*(at*au)));
            float sm=(fhmn*c)*au; *ssmin=sm+sm; *ssmax=fdiv(ga,c+c);
        }
    }
}

__device__ void slasv2(float f,float g,float h,float*ssmin,float*ssmax,
                       float*snr,float*csr,float*snl,float*csl){
    float ft=f, fa=fabsf(f), ht=h, ha=fabsf(h);
    int pmax=1;
    bool swap=(ha>fa);
    if(swap){ pmax=3; float t=ft;ft=ht;ht=t; t=fa;fa=ha;ha=t; }
    float gt=g, ga=fabsf(g);
    float clt=0.f,crt=0.f,slt=0.f,srt=0.f;
    if(ga==0.f){ *ssmin=ha; *ssmax=fa; clt=1.f; crt=1.f; slt=0.f; srt=0.f; }
    else{
        bool gasmal=true;
        if(ga>fa){
            pmax=2;
            if(fdiv(fa,ga)<LEPS){
                gasmal=false; *ssmax=ga;
                *ssmin=(ha>1.f)? fdiv(fa,fdiv(ga,ha)) : fdiv(fa,ga)*ha;
                clt=1.f; slt=fdiv(ht,gt); srt=1.f; crt=fdiv(ft,gt);
            }
        }
        if(gasmal){
            float dd=fa-ha;
            float l=(dd==fa)?1.f:fdiv(dd,fa);
            float m=fdiv(gt,ft), t=2.f-l;
            float mm=m*m, tt=t*t;
            float s=fsqrt(tt+mm);
            float r=(l==0.f)?fabsf(m):fsqrt(l*l+mm);
            float a=0.5f*(s+r);
            *ssmin=fdiv(ha,a); *ssmax=fa*a;
            if(mm==0.f){
                t=(l==0.f)? fsign(2.f,ft)*fsign(1.f,gt) : fdiv(gt,fsign(dd,ft))+fdiv(m,t);
            }else t=(fdiv(m,s+t)+fdiv(m,r+l))*(1.f+a);
            l=fsqrt(fmaf(t,t,4.f));
            crt=fdiv(2.f,l); srt=fdiv(t,l);
            clt=fdiv(crt+srt*m,a); slt=fdiv(ht,ft)*fdiv(srt,a);
        }
    }
    if(swap){ *csl=srt; *snl=crt; *csr=slt; *snr=clt; }
    else{ *csl=clt; *snl=slt; *csr=crt; *snr=srt; }
    float ts=0.f;
    if(pmax==1) ts=fsign(1.f,*csr)*fsign(1.f,*csl)*fsign(1.f,f);
    if(pmax==2) ts=fsign(1.f,*snr)*fsign(1.f,*csl)*fsign(1.f,g);
    if(pmax==3) ts=fsign(1.f,*snr)*fsign(1.f,*snl)*fsign(1.f,h);
    *ssmax=fsign(*ssmax,ts);
    *ssmin=fsign(*ssmin,ts*fsign(1.f,f)*fsign(1.f,h));
}

// ===========================================================================
// Generic sbdsqr (k_setup only). VT: N x NC row-major; U: NRU x N row-major.
// ===========================================================================
template<int N,int NC,int NRU>
__device__ void sbdsqr(float* d, float* e, float* VT, float* U){
    const float tol=10.f*LEPS;
    float sminoa=fabsf(d[0]);
    if(sminoa!=0.f){
        float mu=sminoa;
        for(int i=1;i<N;i++){
            mu=fabsf(d[i])*fdiv(mu,mu+fabsf(e[i-1]));
            sminoa=fminf(sminoa,mu);
            if(sminoa==0.f)break;
        }
    }
    sminoa=fdiv(sminoa,fsqrt((float)N));
    float thresh=fmaxf(tol*sminoa,(float)(6*N*N)*LUNFL);
    int m=N, oldll=-1, oldm=-1, idir=0, guard=0;
    float sminl=0.f;
    float wcs[N],wsn[N],wocs[N],wosn[N];
    while(m>1){
        if(++guard>240) break;
        float smax_b=fabsf(d[m-1]);
        int ll=0; bool split=false;
        for(int lll=1;lll<=m-1;lll++){
            ll=m-lll;
            float abss=fabsf(d[ll-1]), abse=fabsf(e[ll-1]);
            if(abse<=thresh){ split=true; break; }
            smax_b=fmaxf(smax_b,fmaxf(abss,abse));
        }
        if(split){
            e[ll-1]=0.f;
            if(ll==m-1){ m=m-1; continue; }
            ll=ll+1;
        }else ll=1;
        if(ll==m-1){
            float sigmn,sigmx,sinr,cosr,sinl,cosl;
            slasv2(d[m-2],e[m-2],d[m-1],&sigmn,&sigmx,&sinr,&cosr,&sinl,&cosl);
            d[m-2]=sigmx; e[m-2]=0.f; d[m-1]=sigmn;
            if(NC>0)for(int c=0;c<NC;c++){
                float x=VT[(m-2)*NC+c],y=VT[(m-1)*NC+c];
                VT[(m-2)*NC+c]=cosr*x+sinr*y; VT[(m-1)*NC+c]=cosr*y-sinr*x;
            }
            if(NRU>0)for(int r=0;r<NRU;r++){
                float x=U[r*N+m-2],y=U[r*N+m-1];
                U[r*N+m-2]=cosl*x+sinl*y; U[r*N+m-1]=cosl*y-sinl*x;
            }
            m=m-2; continue;
        }
        if(ll>oldm||m<oldll)
            idir=(fabsf(d[ll-1])>=fabsf(d[m-1]))?1:2;
        bool cont=false;
        if(idir==1){
            if(fabsf(e[m-2])<=tol*fabsf(d[m-1])){ e[m-2]=0.f; cont=true; }
            if(!cont){
                float mu=fabsf(d[ll-1]); sminl=mu;
                for(int lll=ll;lll<=m-1;lll++){
                    if(fabsf(e[lll-1])<=tol*mu){ e[lll-1]=0.f; cont=true; break; }
                    mu=fabsf(d[lll])*fdiv(mu,mu+fabsf(e[lll-1]));
                    sminl=fminf(sminl,mu);
                }
            }
        }else{
            if(fabsf(e[ll-1])<=tol*fabsf(d[ll-1])){ e[ll-1]=0.f; cont=true; }
            if(!cont){
                float mu=fabsf(d[m-1]); sminl=mu;
                for(int lll=m-1;lll>=ll;lll--){
                    if(fabsf(e[lll-1])<=tol*mu){ e[lll-1]=0.f; cont=true; break; }
                    mu=fabsf(d[lll-1])*fdiv(mu,mu+fabsf(e[lll-1]));
                    sminl=fminf(sminl,mu);
                }
            }
        }
        if(cont) continue;
        oldll=ll; oldm=m;
        float shift=0.f, rr;
        if(!((float)N*tol*fdiv(sminl,smax_b)<=fmaxf(LEPS,0.01f*tol))){
            float sll;
            if(idir==1){ sll=fabsf(d[ll-1]); slas2(d[m-2],e[m-2],d[m-1],&shift,&rr); }
            else       { sll=fabsf(d[m-1]); slas2(d[ll-1],e[ll-1],d[ll],&shift,&rr); }
            if(sll>0.f && fdiv(shift,sll)*fdiv(shift,sll)<LEPS) shift=0.f;
        }
        if(shift==0.f){
            if(idir==1){
                float cs=1.f, oldcs=1.f, sn=0.f, oldsn=0.f, r;
                for(int i=ll;i<=m-1;i++){
                    slartg(d[i-1]*cs,e[i-1],&cs,&sn,&r);
                    if(i>ll) e[i-2]=oldsn*r;
                    slartg(oldcs*r,d[i]*sn,&oldcs,&oldsn,&d[i-1]);
                    wcs[i-ll]=cs; wsn[i-ll]=sn; wocs[i-ll]=oldcs; wosn[i-ll]=oldsn;
                }
                float h=d[m-1]*cs;
                d[m-1]=h*oldcs; e[m-2]=h*oldsn;
                if(NC>0)for(int j=0;j<m-ll;j++){
                    float c_=wcs[j],s_=wsn[j]; int r0=ll-1+j;
                    for(int c=0;c<NC;c++){
                        float tmp=VT[(r0+1)*NC+c];
                        VT[(r0+1)*NC+c]=c_*tmp-s_*VT[r0*NC+c];
                        VT[r0*NC+c]=s_*tmp+c_*VT[r0*NC+c];
                    }
                }
                if(NRU>0)for(int j=0;j<m-ll;j++){
                    float c_=wocs[j],s_=wosn[j]; int c0=ll-1+j;
                    for(int r=0;r<NRU;r++){
                        float tmp=U[r*N+c0+1];
                        U[r*N+c0+1]=c_*tmp-s_*U[r*N+c0];
                        U[r*N+c0]=s_*tmp+c_*U[r*N+c0];
                    }
                }
                if(fabsf(e[m-2])<=thresh) e[m-2]=0.f;
            }else{
                float cs=1.f, oldcs=1.f, sn=0.f, oldsn=0.f, r;
                for(int i=m;i>=ll+1;i--){
                    slartg(d[i-1]*cs,e[i-2],&cs,&sn,&r);
                    if(i<m) e[i-1]=oldsn*r;
                    slartg(oldcs*r,d[i-2]*sn,&oldcs,&oldsn,&d[i-1]);
                    wcs[i-ll-1]=cs; wsn[i-ll-1]=-sn; wocs[i-ll-1]=oldcs; wosn[i-ll-1]=-oldsn;
                }
                float h=d[ll-1]*cs;
                d[ll-1]=h*oldcs; e[ll-1]=h*oldsn;
                if(NC>0)for(int j=m-ll-1;j>=0;j--){
                    float c_=wocs[j],s_=wosn[j]; int r0=ll-1+j;
                    for(int c=0;c<NC;c++){
                        float tmp=VT[(r0+1)*NC+c];
                        VT[(r0+1)*NC+c]=c_*tmp-s_*VT[r0*NC+c];
                        VT[r0*NC+c]=s_*tmp+c_*VT[r0*NC+c];
                    }
                }
                if(NRU>0)for(int j=m-ll-1;j>=0;j--){
                    float c_=wcs[j],s_=wsn[j]; int c0=ll-1+j;
                    for(int r=0;r<NRU;r++){
                        float tmp=U[r*N+c0+1];
                        U[r*N+c0+1]=c_*tmp-s_*U[r*N+c0];
                        U[r*N+c0]=s_*tmp+c_*U[r*N+c0];
                    }
                }
                if(fabsf(e[ll-1])<=thresh) e[ll-1]=0.f;
            }
        }else{
            if(idir==1){
                float f=(fabsf(d[ll-1])-shift)*(fsign(1.f,d[ll-1])+fdiv(shift,d[ll-1]));
                float g=e[ll-1], cosr,sinr,cosl,sinl,r;
                for(int i=ll;i<=m-1;i++){
                    slartg(f,g,&cosr,&sinr,&r);
                    if(i>ll) e[i-2]=r;
                    f=cosr*d[i-1]+sinr*e[i-1];
                    e[i-1]=cosr*e[i-1]-sinr*d[i-1];
                    g=sinr*d[i];
                    d[i]=cosr*d[i];
                    slartg(f,g,&cosl,&sinl,&r);
                    d[i-1]=r;
                    f=cosl*e[i-1]+sinl*d[i];
                    d[i]=cosl*d[i]-sinl*e[i-1];
                    if(i<m-1){ g=sinl*e[i]; e[i]=cosl*e[i]; }
                    wcs[i-ll]=cosr; wsn[i-ll]=sinr; wocs[i-ll]=cosl; wosn[i-ll]=sinl;
                }
                e[m-2]=f;
                if(NC>0)for(int j=0;j<m-ll;j++){
                    float c_=wcs[j],s_=wsn[j]; int r0=ll-1+j;
                    for(int c=0;c<NC;c++){
                        float tmp=VT[(r0+1)*NC+c];
                        VT[(r0+1)*NC+c]=c_*tmp-s_*VT[r0*NC+c];
                        VT[r0*NC+c]=s_*tmp+c_*VT[r0*NC+c];
                    }
                }
                if(NRU>0)for(int j=0;j<m-ll;j++){
                    float c_=wocs[j],s_=wosn[j]; int c0=ll-1+j;
                    for(int r=0;r<NRU;r++){
                        float tmp=U[r*N+c0+1];
                        U[r*N+c0+1]=c_*tmp-s_*U[r*N+c0];
                        U[r*N+c0]=s_*tmp+c_*U[r*N+c0];
                    }
                }
                if(fabsf(e[m-2])<=thresh) e[m-2]=0.f;
            }else{
                float f=(fabsf(d[m-1])-shift)*(fsign(1.f,d[m-1])+fdiv(shift,d[m-1]));
                float g=e[m-2], cosr,sinr,cosl,sinl,r;
                for(int i=m;i>=ll+1;i--){
                    slartg(f,g,&cosr,&sinr,&r);
                    if(i<m) e[i-1]=r;
                    f=cosr*d[i-1]+sinr*e[i-2];
                    e[i-2]=cosr*e[i-2]-sinr*d[i-1];
                    g=sinr*d[i-2];
                    d[i-2]=cosr*d[i-2];
                    slartg(f,g,&cosl,&sinl,&r);
                    d[i-1]=r;
                    f=cosl*e[i-2]+sinl*d[i-2];
                    d[i-2]=cosl*d[i-2]-sinl*e[i-2];
                    if(i>ll+1){ g=sinl*e[i-3]; e[i-3]=cosl*e[i-3]; }
                    wcs[i-ll-1]=cosl; wsn[i-ll-1]=-sinl; wocs[i-ll-1]=cosr; wosn[i-ll-1]=-sinr;
                }
                e[ll-1]=f;
                if(fabsf(e[ll-1])<=thresh) e[ll-1]=0.f;
                if(NC>0)for(int j=m-ll-1;j>=0;j--){
                    float c_=wocs[j],s_=wosn[j]; int r0=ll-1+j;
                    for(int c=0;c<NC;c++){
                        float tmp=VT[(r0+1)*NC+c];
                        VT[(r0+1)*NC+c]=c_*tmp-s_*VT[r0*NC+c];
                        VT[r0*NC+c]=s_*tmp+c_*VT[r0*NC+c];
                    }
                }
                if(NRU>0)for(int j=m-ll-1;j>=0;j--){
                    float c_=wcs[j],s_=wsn[j]; int c0=ll-1+j;
                    for(int r=0;r<NRU;r++){
                        float tmp=U[r*N+c0+1];
                        U[r*N+c0+1]=c_*tmp-s_*U[r*N+c0];
                        U[r*N+c0]=s_*tmp+c_*U[r*N+c0];
                    }
                }
            }
        }
    }
    for(int i=0;i<N;i++){
        if(d[i]<0.f){
            d[i]=-d[i];
            if(NC>0)for(int c=0;c<NC;c++) VT[i*NC+c]=-VT[i*NC+c];
        }
    }
    for(int i=1;i<=N-1;i++){
        int isub=0; float smn=d[0];
        for(int j=1;j<=N-i;j++) if(d[j]<=smn){ isub=j; smn=d[j]; }
        int tg=N-i;
        if(isub!=tg){
            d[isub]=d[tg]; d[tg]=smn;
            if(NC>0)for(int c=0;c<NC;c++){ float t=VT[isub*NC+c]; VT[isub*NC+c]=VT[tg*NC+c]; VT[tg*NC+c]=t; }
            if(NRU>0)for(int r=0;r<NRU;r++){ float t=U[r*N+isub]; U[r*N+isub]=U[r*N+tg]; U[r*N+tg]=t; }
        }
    }
}

// ===========================================================================
// Register-resident bdsqr, N=4, tracking one VT column (y0..y3).
// ===========================================================================
#define DG(i) ((i)==0?d0:((i)==1?d1:((i)==2?d2:d3)))
#define DS(i,v) do{float _t=(v); if((i)==0)d0=_t; else if((i)==1)d1=_t; else if((i)==2)d2=_t; else d3=_t;}while(0)
#define EG(i) ((i)==0?e0:((i)==1?e1:e2))
#define ES(i,v) do{float _t=(v); if((i)==0)e0=_t; else if((i)==1)e1=_t; else e2=_t;}while(0)
#define YG(i) ((i)==0?y0:((i)==1?y1:((i)==2?y2:y3)))
#define YS(i,v) do{float _t=(v); if((i)==0)y0=_t; else if((i)==1)y1=_t; else if((i)==2)y2=_t; else y3=_t;}while(0)
#define YROT(r0,c_,s_) do{ float _c=(c_), _s=(s_);                            \
    if((r0)==0){ float _t=y1; y1=_c*_t-_s*y0; y0=_s*_t+_c*y0; }               \
    else if((r0)==1){ float _t=y2; y2=_c*_t-_s*y1; y1=_s*_t+_c*y1; }          \
    else { float _t=y3; y3=_c*_t-_s*y2; y2=_s*_t+_c*y2; } }while(0)

__device__ __forceinline__ void bdsqr41(float&d0,float&d1,float&d2,float&d3,
                        float&e0,float&e1,float&e2,
                        float&y0,float&y1,float&y2,float&y3){
    const float tol=10.f*LEPS;
    float sminoa=fabsf(d0);
    if(sminoa!=0.f){
        float mu=sminoa; bool z=false;
#pragma unroll
        for(int i=1;i<4;i++){
            if(!z){
                mu=fabsf(DG(i))*fdiv(mu,mu+fabsf(EG(i-1)));
                sminoa=fminf(sminoa,mu);
                if(sminoa==0.f) z=true;
            }
        }
    }
    sminoa*=0.5f;
    float thresh=fmaxf(tol*sminoa,96.0f*LUNFL);
    int m=4, oldll=-1, oldm=-1, idir=0, guard=0;
    float sminl=0.f;
    while(m>1){
        if(++guard>240) break;
        float smax_b=fabsf(DG(m-1));
        int ll=1; bool split=false;
#pragma unroll
        for(int lll=1;lll<=3;lll++){
            if(!split && lll<=m-1){
                int l2=m-lll;
                float abss=fabsf(DG(l2-1)), abse=fabsf(EG(l2-1));
                if(abse<=thresh){ ll=l2; split=true; }
                else smax_b=fmaxf(smax_b,fmaxf(abss,abse));
            }
        }
        if(split){
            ES(ll-1,0.f);
            if(ll==m-1){ m=m-1; continue; }
            ll=ll+1;
        }
        if(ll==m-1){
            float sigmn,sigmx,sinr,cosr,sinl,cosl;
            slasv2(DG(m-2),EG(m-2),DG(m-1),&sigmn,&sigmx,&sinr,&cosr,&sinl,&cosl);
            DS(m-2,sigmx); ES(m-2,0.f); DS(m-1,sigmn);
            YROT(m-2,cosr,sinr);
            m=m-2; continue;
        }
        if(ll>oldm||m<oldll)
            idir=(fabsf(DG(ll-1))>=fabsf(DG(m-1)))?1:2;
        bool cont=false;
        if(idir==1){
            if(fabsf(EG(m-2))<=tol*fabsf(DG(m-1))){ ES(m-2,0.f); cont=true; }
            if(!cont){
                float mu=fabsf(DG(ll-1)); sminl=mu;
#pragma unroll
                for(int lll=1;lll<=3;lll++){
                    if(!cont && lll>=ll && lll<=m-1){
                        if(fabsf(EG(lll-1))<=tol*mu){ ES(lll-1,0.f); cont=true; }
                        else{
                            mu=fabsf(DG(lll))*fdiv(mu,mu+fabsf(EG(lll-1)));
                            sminl=fminf(sminl,mu);
                        }
                    }
                }
            }
        }else{
            if(fabsf(EG(ll-1))<=tol*fabsf(DG(ll-1))){ ES(ll-1,0.f); cont=true; }
            if(!cont){
                float mu=fabsf(DG(m-1)); sminl=mu;
#pragma unroll
                for(int lll=3;lll>=1;lll--){
                    if(!cont && lll>=ll && lll<=m-1){
                        if(fabsf(EG(lll-1))<=tol*mu){ ES(lll-1,0.f); cont=true; }
                        else{
                            mu=fabsf(DG(lll-1))*fdiv(mu,mu+fabsf(EG(lll-1)));
                            sminl=fminf(sminl,mu);
                        }
                    }
                }
            }
        }
        if(cont) continue;
        oldll=ll; oldm=m;
        float shift=0.f, rr;
        if(!(4.0f*tol*fdiv(sminl,smax_b)<=fmaxf(LEPS,0.01f*tol))){
            float sll;
            if(idir==1){ sll=fabsf(DG(ll-1)); slas2(DG(m-2),EG(m-2),DG(m-1),&shift,&rr); }
            else       { sll=fabsf(DG(m-1)); slas2(DG(ll-1),EG(ll-1),DG(ll),&shift,&rr); }
            if(sll>0.f && fdiv(shift,sll)*fdiv(shift,sll)<LEPS) shift=0.f;
        }
        if(shift==0.f){
            if(idir==1){
                float cs=1.f, oldcs=1.f, sn=0.f, oldsn=0.f, r;
#pragma unroll
                for(int i=1;i<=3;i++){
                    if(i>=ll && i<=m-1){
                        slartg(DG(i-1)*cs,EG(i-1),&cs,&sn,&r);
                        if(i>ll) ES(i-2,oldsn*r);
                        float dn; slartg(oldcs*r,DG(i)*sn,&oldcs,&oldsn,&dn);
                        DS(i-1,dn);
                        YROT(i-1,cs,sn);
                    }
                }
                float h=DG(m-1)*cs;
                DS(m-1,h*oldcs); ES(m-2,h*oldsn);
                if(fabsf(EG(m-2))<=thresh) ES(m-2,0.f);
            }else{
                float cs=1.f, oldcs=1.f, sn=0.f, oldsn=0.f, r;
#pragma unroll
                for(int i=4;i>=2;i--){
                    if(i<=m && i>=ll+1){
                        slartg(DG(i-1)*cs,EG(i-2),&cs,&sn,&r);
                        if(i<m) ES(i-1,oldsn*r);
                        float dn; slartg(oldcs*r,DG(i-2)*sn,&oldcs,&oldsn,&dn);
                        DS(i-1,dn);
                        YROT(i-2,oldcs,-oldsn);
                    }
                }
                float h=DG(ll-1)*cs;
                DS(ll-1,h*oldcs); ES(ll-1,h*oldsn);
                if(fabsf(EG(ll-1))<=thresh) ES(ll-1,0.f);
            }
        }else{
            if(idir==1){
                float f=(fabsf(DG(ll-1))-shift)*(fsign(1.f,DG(ll-1))+fdiv(shift,DG(ll-1)));
                float g=EG(ll-1), cosr,sinr,cosl,sinl,r;
#pragma unroll
                for(int i=1;i<=3;i++){
                    if(i>=ll && i<=m-1){
                        slartg(f,g,&cosr,&sinr,&r);
                        if(i>ll) ES(i-2,r);
                        float di1=DG(i-1), ei1=EG(i-1), di=DG(i);
                        f=cosr*di1+sinr*ei1;
                        float ei1n=cosr*ei1-sinr*di1;
                        g=sinr*di;
                        float din=cosr*di;
                        slartg(f,g,&cosl,&sinl,&r);
                        DS(i-1,r);
                        f=cosl*ei1n+sinl*din;
                        DS(i,cosl*din-sinl*ei1n);
                        ES(i-1,ei1n);
                        if(i<m-1){ float ei=EG(i); g=sinl*ei; ES(i,cosl*ei); }
                        YROT(i-1,cosr,sinr);
                    }
                }
                ES(m-2,f);
                if(fabsf(EG(m-2))<=thresh) ES(m-2,0.f);
            }else{
                float f=(fabsf(DG(m-1))-shift)*(fsign(1.f,DG(m-1))+fdiv(shift,DG(m-1)));
                float g=EG(m-2), cosr,sinr,cosl,sinl,r;
#pragma unroll
                for(int i=4;i>=2;i--){
                    if(i<=m && i>=ll+1){
                        slartg(f,g,&cosr,&sinr,&r);
                        if(i<m) ES(i-1,r);
                        float di1=DG(i-1), ei2=EG(i-2), di2=DG(i-2);
                        f=cosr*di1+sinr*ei2;
                        float ei2n=cosr*ei2-sinr*di1;
                        g=sinr*di2;
                        float di2n=cosr*di2;
                        slartg(f,g,&cosl,&sinl,&r);
                        DS(i-1,r);
                        f=cosl*ei2n+sinl*di2n;
                        DS(i-2,cosl*di2n-sinl*ei2n);
                        ES(i-2,ei2n);
                        if(i>ll+1){ float ei3=EG(i-3); g=sinl*ei3; ES(i-3,cosl*ei3); }
                        YROT(i-2,cosr,-sinr);
                    }
                }
                ES(ll-1,f);
                if(fabsf(EG(ll-1))<=thresh) ES(ll-1,0.f);
            }
        }
    }
    if(d0<0.f){ d0=-d0; y0=-y0; }
    if(d1<0.f){ d1=-d1; y1=-y1; }
    if(d2<0.f){ d2=-d2; y2=-y2; }
    if(d3<0.f){ d3=-d3; y3=-y3; }
#pragma unroll
    for(int i=1;i<=3;i++){
        int isub=0; float smn=d0;
#pragma unroll
        for(int j=1;j<=3;j++){
            if(j<=4-i && DG(j)<=smn){ isub=j; smn=DG(j); }
        }
        int tg=4-i;
        if(isub!=tg){
            DS(isub,DG(tg)); DS(tg,smn);
            float t=YG(isub); YS(isub,YG(tg)); YS(tg,t);
        }
    }
}

// one family (+t). Build A, sgebd2 (n=4), track y = P^T e3, bdsqr41.
__device__ __forceinline__ void solve_fam(const float* __restrict__ P,
                                       float p1x,float p1y,float p2x,float p2y,
                                       float* z1o, float* wo){
    float A[4][4];
    A[0][0]=-1.f; A[0][1]=0.f;  A[0][2]=p1x; A[0][3]=0.f;
    A[1][0]=0.f;  A[1][1]=-1.f; A[1][2]=p1y; A[1][3]=0.f;
    A[2][0]=p2x*P[8]-P[0]; A[2][1]=p2x*P[9]-P[1];
    A[2][2]=p2x*P[10]-P[2]; A[2][3]=p2x*P[11]-P[3];
    A[3][0]=p2y*P[8]-P[4]; A[3][1]=p2y*P[9]-P[5];
    A[3][2]=p2y*P[10]-P[6]; A[3][3]=p2y*P[11]-P[7];

    float d[4], e[3], tauq[4], taup[3];
#pragma unroll
    for(int i=0;i<4;i++){
        float alpha=A[i][i], xn=0.f;
#pragma unroll
        for(int k=0;k<4;k++) if(k>i) xn+=A[k][i]*A[k][i];
        xn=fsqrt(xn);
        if(xn==0.f){ tauq[i]=0.f; d[i]=alpha; }
        else{
            float beta=-fsign(fsqrt(fmaf(alpha,alpha,xn*xn)),alpha);
            tauq[i]=fdiv(beta-alpha,beta);
            float sc=fdiv(1.f,alpha-beta);
#pragma unroll
            for(int k=0;k<4;k++) if(k>i) A[k][i]*=sc;
            d[i]=beta;
        }
        if(i<3){
#pragma unroll
            for(int j=0;j<4;j++) if(j>i){
                float w=A[i][j];
#pragma unroll
                for(int k=0;k<4;k++) if(k>i) w+=A[k][i]*A[k][j];
                w*=tauq[i];
                A[i][j]-=w;
#pragma unroll
                for(int k=0;k<4;k++) if(k>i) A[k][j]-=w*A[k][i];
            }
            float al2=A[i][i+1], xn2=0.f;
#pragma unroll
            for(int k=0;k<4;k++) if(k>i+1) xn2+=A[i][k]*A[i][k];
            xn2=fsqrt(xn2);
            if(xn2==0.f){ taup[i]=0.f; e[i]=al2; }
            else{
                float beta=-fsign(fsqrt(fmaf(al2,al2,xn2*xn2)),al2);
                taup[i]=fdiv(beta-al2,beta);
                float sc=fdiv(1.f,al2-beta);
#pragma unroll
                for(int k=0;k<4;k++) if(k>i+1) A[i][k]*=sc;
                e[i]=beta;
            }
#pragma unroll
            for(int r=0;r<4;r++) if(r>i){
                float w=A[r][i+1];
#pragma unroll
                for(int k=0;k<4;k++) if(k>i+1) w+=A[i][k]*A[r][k];
                w*=taup[i];
                A[r][i+1]-=w;
#pragma unroll
                for(int k=0;k<4;k++) if(k>i+1) A[r][k]-=w*A[i][k];
            }
        }
    }
    float y0=0.f,y1=0.f,y2=0.f,y3=1.f;
    {   float w=(y1+A[0][2]*y2+A[0][3]*y3)*taup[0];
        y1-=w; y2-=w*A[0][2]; y3-=w*A[0][3]; }
    {   float w=(y2+A[1][3]*y3)*taup[1];
        y2-=w; y3-=w*A[1][3]; }

    float d0=d[0],d1=d[1],d2=d[2],d3=d[3],e0=e[0],e1=e[1],e2=e[2];
    bdsqr41(d0,d1,d2,d3,e0,e1,e2,y0,y1,y2,y3);

    float iy3=fdiv(1.f,y3);
    float pd0=y0*iy3, pd1=y1*iy3, pd2=y2*iy3;
    *z1o=pd2;
    *wo=P[8]*pd0+P[9]*pd1+P[10]*pd2;
}

// ---------------------------------------------------------------------------
// k_setup: 32 blocks x 1 thread — zero intra-warp divergence per batch.
// ---------------------------------------------------------------------------
__global__ void k_setup(const float* __restrict__ Fin, const float* __restrict__ Kin){
    int b=blockIdx.x;
    if(threadIdx.x!=0 || b>=NB) return;
    g_scores[b][0]=0; g_scores[b][1]=0; g_scores[b][2]=0; g_scores[b][3]=0;
    g_counts[b]=0;

    float Km[3][3], Fm[3][3];
#pragma unroll
    for(int r=0;r<3;++r)
#pragma unroll
        for(int c=0;c<3;++c){ Km[r][c]=Kin[b*9+r*3+c]; Fm[r][c]=Fin[b*9+r*3+c]; }
    float T[3][3], A3[3][3];
#pragma unroll
    for(int i=0;i<3;++i)
#pragma unroll
        for(int j=0;j<3;++j){
            float s=0.f;
#pragma unroll
            for(int k=0;k<3;++k) s=fmaf(Km[k][i],Fm[k][j],s);
            T[i][j]=s; }
#pragma unroll
    for(int i=0;i<3;++i)
#pragma unroll
        for(int j=0;j<3;++j){
            float s=0.f;
#pragma unroll
            for(int k=0;k<3;++k) s=fmaf(T[i][k],Km[k][j],s);
            A3[i][j]=s; }

    float d[3], e[2], tauq[3], taup[2];
#pragma unroll
    for(int i=0;i<3;i++){
        float alpha=A3[i][i], xn=0.f;
#pragma unroll
        for(int k=0;k<3;k++) if(k>i) xn+=A3[k][i]*A3[k][i];
        xn=fsqrt(xn);
        if(xn==0.f){ tauq[i]=0.f; d[i]=alpha; }
        else{
            float beta=-fsign(fsqrt(fmaf(alpha,alpha,xn*xn)),alpha);
            tauq[i]=fdiv(beta-alpha,beta);
            float sc=fdiv(1.f,alpha-beta);
#pragma unroll
            for(int k=0;k<3;k++) if(k>i) A3[k][i]*=sc;
            d[i]=beta;
        }
        if(i<2){
#pragma unroll
            for(int j=0;j<3;j++) if(j>i){
                float w=A3[i][j];
#pragma unroll
                for(int k=0;k<3;k++) if(k>i) w+=A3[k][i]*A3[k][j];
                w*=tauq[i];
                A3[i][j]-=w;
#pragma unroll
                for(int k=0;k<3;k++) if(k>i) A3[k][j]-=w*A3[k][i];
            }
            float al2=A3[i][i+1], xn2=0.f;
#pragma unroll
            for(int k=0;k<3;k++) if(k>i+1) xn2+=A3[i][k]*A3[i][k];
            xn2=fsqrt(xn2);
            if(xn2==0.f){ taup[i]=0.f; e[i]=al2; }
            else{
                float beta=-fsign(fsqrt(fmaf(al2,al2,xn2*xn2)),al2);
                taup[i]=fdiv(beta-al2,beta);
                float sc=fdiv(1.f,al2-beta);
#pragma unroll
                for(int k=0;k<3;k++) if(k>i+1) A3[i][k]*=sc;
                e[i]=beta;
            }
#pragma unroll
            for(int r=0;r<3;r++) if(r>i){
                float w=A3[r][i+1];
#pragma unroll
                for(int k=0;k<3;k++) if(k>i+1) w+=A3[i][k]*A3[r][k];
                w*=taup[i];
                A3[r][i+1]-=w;
#pragma unroll
                for(int k=0;k<3;k++) if(k>i+1) A3[r][k]-=w*A3[i][k];
            }
        }
    }
    float Ub[9]={1,0,0,0,1,0,0,0,1}, VTb[9]={1,0,0,0,1,0,0,0,1};
    sbdsqr<3,3,3>(d,e,VTb,Ub);
    float U[3][3], VT[3][3];
#pragma unroll
    for(int c=0;c<3;c++){
        float x0=Ub[0*3+c], x1=Ub[1*3+c], x2=Ub[2*3+c];
        float w=(x1+A3[2][1]*x2)*tauq[1];
        x1-=w; x2-=w*A3[2][1];
        w=(x0+A3[1][0]*x1+A3[2][0]*x2)*tauq[0];
        x0-=w; x1-=w*A3[1][0]; x2-=w*A3[2][0];
        U[0][c]=x0; U[1][c]=x1; U[2][c]=x2;
    }
#pragma unroll
    for(int r=0;r<3;r++){
        float w=(VTb[r*3+1]+A3[0][2]*VTb[r*3+2])*taup[0];
        VT[r][0]=VTb[r*3+0]; VT[r][1]=VTb[r*3+1]-w; VT[r][2]=VTb[r*3+2]-w*A3[0][2];
    }
    float dU = U[0][0]*(U[1][1]*U[2][2]-U[1][2]*U[2][1])
             - U[0][1]*(U[1][0]*U[2][2]-U[1][2]*U[2][0])
             + U[0][2]*(U[1][0]*U[2][1]-U[1][1]*U[2][0]);
    float dV = VT[0][0]*(VT[1][1]*VT[2][2]-VT[1][2]*VT[2][1])
             - VT[0][1]*(VT[1][0]*VT[2][2]-VT[1][2]*VT[2][0])
             + VT[0][2]*(VT[1][0]*VT[2][1]-VT[1][1]*VT[2][0]);
    float sU=(dU<0.f)?-1.f:1.f, sV=(dV<0.f)?-1.f:1.f;
#pragma unroll
    for(int r=0;r<3;r++)
#pragma unroll
        for(int c=0;c<3;c++){ U[r][c]*=sU; VT[r][c]*=sV; }

#pragma unroll
    for(int i=0;i<3;i++){
#pragma unroll
        for(int j=0;j<3;j++){
            float r1= U[i][1]*VT[j][0] - U[i][0]*VT[j][1] + U[i][2]*VT[j][2];
            float r2=-U[i][1]*VT[j][0] + U[i][0]*VT[j][1] + U[i][2]*VT[j][2];
            g_P2[b][0][i*4+j]=r1;
            g_P2[b][1][i*4+j]=r2;
        }
        g_P2[b][0][i*4+3]=U[i][2];
        g_P2[b][1][i*4+3]=U[i][2];
    }
    float f=Km[0][0];
    g_Kn[b][0]=1.0f/f;
    g_Kn[b][1]=-(Km[0][2]/f);
    g_Kn[b][2]=-(Km[1][2]/f);
    g_Kn[b][3]=0.f;
}

// ---------------------------------------------------------------------------
__global__ void __launch_bounds__(256) k_points(
        const float* __restrict__ p1s, const float* __restrict__ p2s,
        const int* __restrict__ bidx, int n){
    int i=blockIdx.x*blockDim.x+threadIdx.x;
    bool act=i<n;
    int b=0;
    bool bit0=false,bit1=false,bit2=false,bit3=false;
    if(act){
        b=bidx[i];
        float invf=g_Kn[b][0], k02=g_Kn[b][1], k12=g_Kn[b][2];
        float p1x=fmaf(invf,p1s[2*i+0],k02);
        float p1y=fmaf(invf,p1s[2*i+1],k12);
        float p2x=fmaf(invf,p2s[2*i+0],k02);
        float p2y=fmaf(invf,p2s[2*i+1],k12);
        const float* P0=g_P2[b][0];
        const float* P1=g_P2[b][1];
        float z1a,wa,z1b,wb;
        solve_fam(P0,p1x,p1y,p2x,p2y,&z1a,&wa);
        solve_fam(P1,p1x,p1y,p2x,p2y,&z1b,&wb);
        float t2a=P0[11], t2b=P1[11];
        bit0=(z1a>0.f)&&(wa+t2a>0.f);
        bit1=(z1a>0.f)&&(wa-t2a>0.f);
        bit2=(z1b>0.f)&&(wb+t2b>0.f);
        bit3=(z1b>0.f)&&(wb-t2b>0.f);
    }
    const unsigned full=0xffffffffu;
    int bkey=act?b:-1;
    int bmax=__reduce_max_sync(full,bkey);
    bool uni=__all_sync(full,(!act)||(bkey==bmax));
    if(uni){
        if(bmax>=0){
            unsigned ba=__ballot_sync(full,act);
            unsigned m0=__ballot_sync(full,act&&bit0);
            unsigned m1=__ballot_sync(full,act&&bit1);
            unsigned m2=__ballot_sync(full,act&&bit2);
            unsigned m3=__ballot_sync(full,act&&bit3);
            if((threadIdx.x&31)==0){
                if(m0) atomicAdd(&g_scores[bmax][0],__popc(m0));
                if(m1) atomicAdd(&g_scores[bmax][1],__popc(m1));
                if(m2) atomicAdd(&g_scores[bmax][2],__popc(m2));
                if(m3) atomicAdd(&g_scores[bmax][3],__popc(m3));
                atomicAdd(&g_counts[bmax],__popc(ba));
            }
        }
    }else if(act){
        if(bit0) atomicAdd(&g_scores[b][0],1);
        if(bit1) atomicAdd(&g_scores[b][1],1);
        if(bit2) atomicAdd(&g_scores[b][2],1);
        if(bit3) atomicAdd(&g_scores[b][3],1);
        atomicAdd(&g_counts[b],1);
    }
}

// ---------------------------------------------------------------------------
__global__ void k_final(float* __restrict__ out, int out_size){
    int b=threadIdx.x;
    if(b>=NB) return;
    int s0=g_scores[b][0],s1=g_scores[b][1],s2=g_scores[b][2],s3=g_scores[b][3];
    int best=0, sm=s0;
    if(s1>sm){best=1;sm=s1;}
    if(s2>sm){best=2;sm=s2;}
    if(s3>sm){best=3;sm=s3;}
    int cnt=g_counts[b];
    float has=(cnt>0)?1.f:0.f;
    int fam=best>>1;
    float sgn=(best&1)?-1.f:1.f;
    const float* P=g_P2[b][fam];
#pragma unroll
    for(int r=0;r<3;r++)
#pragma unroll
        for(int c=0;c<3;c++)
            out[b*9+r*3+c]=P[r*4+c]*has;
    if(out_size>=NB*9+NB*3){
#pragma unroll
        for(int r=0;r<3;r++)
            out[NB*9+b*3+r]=sgn*P[r*4+3]*has;
    }
    if(out_size>=NB*9+NB*3+NB)
        out[NB*9+NB*3+b]=(float)((cnt>0)?best:0);
}

extern "C" void kernel_launch(void* const* d_in, const int* in_sizes, int n_in,
                              void* d_out, int out_size){
    const float* Fm  =(const float*)d_in[0];
    const float* Km  =(const float*)d_in[1];
    const float* pts1=(const float*)d_in[2];
    const float* pts2=(const float*)d_in[3];
    const int*   bidx=(const int*)d_in[4];
    int n=in_sizes[4];
    float* out=(float*)d_out;

    k_setup<<<NB,1>>>(Fm,Km);
    k_points<<<(n+255)/256,256>>>(pts1,pts2,bidx,n);
    k_final<<<1,32>>>(out,out_size);
}

// round 15
// speedup vs baseline: 1.2774x; 1.2774x over previous
#include <cuda_runtime.h>
#include <cuda_bf16.h>

#define NB 32
#define LEPS 5.9604645e-8f
#define LUNFL 1.1754944e-38f

__device__ float g_P2[NB][2][12];
__device__ float g_Kn[NB][4];
__device__ int   g_scores[NB][4];
__device__ int   g_counts[NB];

__device__ __forceinline__ float fsign(float a, float b){ return copysignf(a,b); }
__device__ __forceinline__ float fdiv(float a, float b){ return __fdividef(a,b); }
__device__ __forceinline__ float fsqrt(float x){ return (x<=0.f)?0.f:x*rsqrtf(x); }

// division-free slartg: one MUFU.RSQ, outputs independent off rs
__device__ __forceinline__ void slartg(float f,float g,float*cs,float*sn,float*r){
    if(g==0.f){ *cs=1.f; *sn=0.f; *r=f; }
    else if(f==0.f){ *cs=0.f; *sn=fsign(1.f,g); *r=fabsf(g); }
    else{
        float s2=fmaf(f,f,g*g);
        float rs=rsqrtf(s2);
        float d=s2*rs;
        *cs=fabsf(f)*rs;
        *r=fsign(d,f);
        *sn=g*rs*fsign(1.f,f);
    }
}

__device__ void slas2(float f,float g,float h,float*ssmin,float*ssmax){
    float fa=fabsf(f), ga=fabsf(g), ha=fabsf(h);
    float fhmn=fminf(fa,ha), fhmx=fmaxf(fa,ha);
    if(fhmn==0.f){
        *ssmin=0.f;
        if(fhmx==0.f) *ssmax=ga;
        else{ float mn=fminf(fhmx,ga), mx=fmaxf(fhmx,ga);
              float q=fdiv(mn,mx); *ssmax=mx*fsqrt(1.f+q*q); }
    }else if(ga<fhmx){
        float as=1.f+fdiv(fhmn,fhmx), at=fdiv(fhmx-fhmn,fhmx), au=fdiv(ga,fhmx)*fdiv(ga,fhmx);
        float c=fdiv(2.f,fsqrt(as*as+au)+fsqrt(at*at+au));
        *ssmin=fhmn*c; *ssmax=fdiv(fhmx,c);
    }else{
        float au=fdiv(fhmx,ga);
        if(au==0.f){ *ssmin=fdiv(fhmn*fhmx,ga); *ssmax=ga; }
        else{
            float as=1.f+fdiv(fhmn,fhmx), at=fdiv(fhmx-fhmn,fhmx);
            float c=fdiv(1.f,fsqrt(1.f+(as*au)*(as*au))+fsqrt(1.f+(at*au)*(at*au)));
            float sm=(fhmn*c)*au; *ssmin=sm+sm; *ssmax=fdiv(ga,c+c);
        }
    }
}

__device__ void slasv2(float f,float g,float h,float*ssmin,float*ssmax,
                       float*snr,float*csr,float*snl,float*csl){
    float ft=f, fa=fabsf(f), ht=h, ha=fabsf(h);
    int pmax=1;
    bool swap=(ha>fa);
    if(swap){ pmax=3; float t=ft;ft=ht;ht=t; t=fa;fa=ha;ha=t; }
    float gt=g, ga=fabsf(g);
    float clt=0.f,crt=0.f,slt=0.f,srt=0.f;
    if(ga==0.f){ *ssmin=ha; *ssmax=fa; clt=1.f; crt=1.f; slt=0.f; srt=0.f; }
    else{
        bool gasmal=true;
        if(ga>fa){
            pmax=2;
            if(fdiv(fa,ga)<LEPS){
                gasmal=false; *ssmax=ga;
                *ssmin=(ha>1.f)? fdiv(fa,fdiv(ga,ha)) : fdiv(fa,ga)*ha;
                clt=1.f; slt=fdiv(ht,gt); srt=1.f; crt=fdiv(ft,gt);
            }
        }
        if(gasmal){
            float dd=fa-ha;
            float l=(dd==fa)?1.f:fdiv(dd,fa);
            float m=fdiv(gt,ft), t=2.f-l;
            float mm=m*m, tt=t*t;
            float s=fsqrt(tt+mm);
            float r=(l==0.f)?fabsf(m):fsqrt(l*l+mm);
            float a=0.5f*(s+r);
            *ssmin=fdiv(ha,a); *ssmax=fa*a;
            if(mm==0.f){
                t=(l==0.f)? fsign(2.f,ft)*fsign(1.f,gt) : fdiv(gt,fsign(dd,ft))+fdiv(m,t);
            }else t=(fdiv(m,s+t)+fdiv(m,r+l))*(1.f+a);
            l=fsqrt(fmaf(t,t,4.f));
            crt=fdiv(2.f,l); srt=fdiv(t,l);
            clt=fdiv(crt+srt*m,a); slt=fdiv(ht,ft)*fdiv(srt,a);
        }
    }
    if(swap){ *csl=srt; *snl=crt; *csr=slt; *snr=clt; }
    else{ *csl=clt; *snl=slt; *csr=crt; *snr=srt; }
    float ts=0.f;
    if(pmax==1) ts=fsign(1.f,*csr)*fsign(1.f,*csl)*fsign(1.f,f);
    if(pmax==2) ts=fsign(1.f,*snr)*fsign(1.f,*csl)*fsign(1.f,g);
    if(pmax==3) ts=fsign(1.f,*snr)*fsign(1.f,*snl)*fsign(1.f,h);
    *ssmax=fsign(*ssmax,ts);
    *ssmin=fsign(*ssmin,ts*fsign(1.f,f)*fsign(1.f,h));
}

// ===========================================================================
// Generic sbdsqr (k_setup only). VT: N x NC row-major; U: NRU x N row-major.
// ===========================================================================
template<int N,int NC,int NRU>
__device__ void sbdsqr(float* d, float* e, float* VT, float* U){
    const float tol=10.f*LEPS;
    float sminoa=fabsf(d[0]);
    if(sminoa!=0.f){
        float mu=sminoa;
        for(int i=1;i<N;i++){
            mu=fabsf(d[i])*fdiv(mu,mu+fabsf(e[i-1]));
            sminoa=fminf(sminoa,mu);
            if(sminoa==0.f)break;
        }
    }
    sminoa=fdiv(sminoa,fsqrt((float)N));
    float thresh=fmaxf(tol*sminoa,(float)(6*N*N)*LUNFL);
    int m=N, oldll=-1, oldm=-1, idir=0, guard=0;
    float sminl=0.f;
    float wcs[N],wsn[N],wocs[N],wosn[N];
    while(m>1){
        if(++guard>240) break;
        float smax_b=fabsf(d[m-1]);
        int ll=0; bool split=false;
        for(int lll=1;lll<=m-1;lll++){
            ll=m-lll;
            float abss=fabsf(d[ll-1]), abse=fabsf(e[ll-1]);
            if(abse<=thresh){ split=true; break; }
            smax_b=fmaxf(smax_b,fmaxf(abss,abse));
        }
        if(split){
            e[ll-1]=0.f;
            if(ll==m-1){ m=m-1; continue; }
            ll=ll+1;
        }else ll=1;
        if(ll==m-1){
            float sigmn,sigmx,sinr,cosr,sinl,cosl;
            slasv2(d[m-2],e[m-2],d[m-1],&sigmn,&sigmx,&sinr,&cosr,&sinl,&cosl);
            d[m-2]=sigmx; e[m-2]=0.f; d[m-1]=sigmn;
            if(NC>0)for(int c=0;c<NC;c++){
                float x=VT[(m-2)*NC+c],y=VT[(m-1)*NC+c];
                VT[(m-2)*NC+c]=cosr*x+sinr*y; VT[(m-1)*NC+c]=cosr*y-sinr*x;
            }
            if(NRU>0)for(int r=0;r<NRU;r++){
                float x=U[r*N+m-2],y=U[r*N+m-1];
                U[r*N+m-2]=cosl*x+sinl*y; U[r*N+m-1]=cosl*y-sinl*x;
            }
            m=m-2; continue;
        }
        if(ll>oldm||m<oldll)
            idir=(fabsf(d[ll-1])>=fabsf(d[m-1]))?1:2;
        bool cont=false;
        if(idir==1){
            if(fabsf(e[m-2])<=tol*fabsf(d[m-1])){ e[m-2]=0.f; cont=true; }
            if(!cont){
                float mu=fabsf(d[ll-1]); sminl=mu;
                for(int lll=ll;lll<=m-1;lll++){
                    if(fabsf(e[lll-1])<=tol*mu){ e[lll-1]=0.f; cont=true; break; }
                    mu=fabsf(d[lll])*fdiv(mu,mu+fabsf(e[lll-1]));
                    sminl=fminf(sminl,mu);
                }
            }
        }else{
            if(fabsf(e[ll-1])<=tol*fabsf(d[ll-1])){ e[ll-1]=0.f; cont=true; }
            if(!cont){
                float mu=fabsf(d[m-1]); sminl=mu;
                for(int lll=m-1;lll>=ll;lll--){
                    if(fabsf(e[lll-1])<=tol*mu){ e[lll-1]=0.f; cont=true; break; }
                    mu=fabsf(d[lll-1])*fdiv(mu,mu+fabsf(e[lll-1]));
                    sminl=fminf(sminl,mu);
                }
            }
        }
        if(cont) continue;
        oldll=ll; oldm=m;
        float shift=0.f, rr;
        if(!((float)N*tol*fdiv(sminl,smax_b)<=fmaxf(LEPS,0.01f*tol))){
            float sll;
            if(idir==1){ sll=fabsf(d[ll-1]); slas2(d[m-2],e[m-2],d[m-1],&shift,&rr); }
            else       { sll=fabsf(d[m-1]); slas2(d[ll-1],e[ll-1],d[ll],&shift,&rr); }
            if(sll>0.f && fdiv(shift,sll)*fdiv(shift,sll)<LEPS) shift=0.f;
        }
        if(shift==0.f){
            if(idir==1){
                float cs=1.f, oldcs=1.f, sn=0.f, oldsn=0.f, r;
                for(int i=ll;i<=m-1;i++){
                    slartg(d[i-1]*cs,e[i-1],&cs,&sn,&r);
                    if(i>ll) e[i-2]=oldsn*r;
                    slartg(oldcs*r,d[i]*sn,&oldcs,&oldsn,&d[i-1]);
                    wcs[i-ll]=cs; wsn[i-ll]=sn; wocs[i-ll]=oldcs; wosn[i-ll]=oldsn;
                }
                float h=d[m-1]*cs;
                d[m-1]=h*oldcs; e[m-2]=h*oldsn;
                if(NC>0)for(int j=0;j<m-ll;j++){
                    float c_=wcs[j],s_=wsn[j]; int r0=ll-1+j;
                    for(int c=0;c<NC;c++){
                        float tmp=VT[(r0+1)*NC+c];
                        VT[(r0+1)*NC+c]=c_*tmp-s_*VT[r0*NC+c];
                        VT[r0*NC+c]=s_*tmp+c_*VT[r0*NC+c];
                    }
                }
                if(NRU>0)for(int j=0;j<m-ll;j++){
                    float c_=wocs[j],s_=wosn[j]; int c0=ll-1+j;
                    for(int r=0;r<NRU;r++){
                        float tmp=U[r*N+c0+1];
                        U[r*N+c0+1]=c_*tmp-s_*U[r*N+c0];
                        U[r*N+c0]=s_*tmp+c_*U[r*N+c0];
                    }
                }
                if(fabsf(e[m-2])<=thresh) e[m-2]=0.f;
            }else{
                float cs=1.f, oldcs=1.f, sn=0.f, oldsn=0.f, r;
                for(int i=m;i>=ll+1;i--){
                    slartg(d[i-1]*cs,e[i-2],&cs,&sn,&r);
                    if(i<m) e[i-1]=oldsn*r;
                    slartg(oldcs*r,d[i-2]*sn,&oldcs,&oldsn,&d[i-1]);
                    wcs[i-ll-1]=cs; wsn[i-ll-1]=-sn; wocs[i-ll-1]=oldcs; wosn[i-ll-1]=-oldsn;
                }
                float h=d[ll-1]*cs;
                d[ll-1]=h*oldcs; e[ll-1]=h*oldsn;
                if(NC>0)for(int j=m-ll-1;j>=0;j--){
                    float c_=wocs[j],s_=wosn[j]; int r0=ll-1+j;
                    for(int c=0;c<NC;c++){
                        float tmp=VT[(r0+1)*NC+c];
                        VT[(r0+1)*NC+c]=c_*tmp-s_*VT[r0*NC+c];
                        VT[r0*NC+c]=s_*tmp+c_*VT[r0*NC+c];
                    }
                }
                if(NRU>0)for(int j=m-ll-1;j>=0;j--){
                    float c_=wcs[j],s_=wsn[j]; int c0=ll-1+j;
                    for(int r=0;r<NRU;r++){
                        float tmp=U[r*N+c0+1];
                        U[r*N+c0+1]=c_*tmp-s_*U[r*N+c0];
                        U[r*N+c0]=s_*tmp+c_*U[r*N+c0];
                    }
                }
                if(fabsf(e[ll-1])<=thresh) e[ll-1]=0.f;
            }
        }else{
            if(idir==1){
                float f=(fabsf(d[ll-1])-shift)*(fsign(1.f,d[ll-1])+fdiv(shift,d[ll-1]));
                float g=e[ll-1], cosr,sinr,cosl,sinl,r;
                for(int i=ll;i<=m-1;i++){
                    slartg(f,g,&cosr,&sinr,&r);
                    if(i>ll) e[i-2]=r;
                    f=cosr*d[i-1]+sinr*e[i-1];
                    e[i-1]=cosr*e[i-1]-sinr*d[i-1];
                    g=sinr*d[i];
                    d[i]=cosr*d[i];
                    slartg(f,g,&cosl,&sinl,&r);
                    d[i-1]=r;
                    f=cosl*e[i-1]+sinl*d[i];
                    d[i]=cosl*d[i]-sinl*e[i-1];
                    if(i<m-1){ g=sinl*e[i]; e[i]=cosl*e[i]; }
                    wcs[i-ll]=cosr; wsn[i-ll]=sinr; wocs[i-ll]=cosl; wosn[i-ll]=sinl;
                }
                e[m-2]=f;
                if(NC>0)for(int j=0;j<m-ll;j++){
                    float c_=wcs[j],s_=wsn[j]; int r0=ll-1+j;
                    for(int c=0;c<NC;c++){
                        float tmp=VT[(r0+1)*NC+c];
                        VT[(r0+1)*NC+c]=c_*tmp-s_*VT[r0*NC+c];
                        VT[r0*NC+c]=s_*tmp+c_*VT[r0*NC+c];
                    }
                }
                if(NRU>0)for(int j=0;j<m-ll;j++){
                    float c_=wocs[j],s_=wosn[j]; int c0=ll-1+j;
                    for(int r=0;r<NRU;r++){
                        float tmp=U[r*N+c0+1];
                        U[r*N+c0+1]=c_*tmp-s_*U[r*N+c0];
                        U[r*N+c0]=s_*tmp+c_*U[r*N+c0];
                    }
                }
                if(fabsf(e[m-2])<=thresh) e[m-2]=0.f;
            }else{
                float f=(fabsf(d[m-1])-shift)*(fsign(1.f,d[m-1])+fdiv(shift,d[m-1]));
                float g=e[m-2], cosr,sinr,cosl,sinl,r;
                for(int i=m;i>=ll+1;i--){
                    slartg(f,g,&cosr,&sinr,&r);
                    if(i<m) e[i-1]=r;
                    f=cosr*d[i-1]+sinr*e[i-2];
                    e[i-2]=cosr*e[i-2]-sinr*d[i-1];
                    g=sinr*d[i-2];
                    d[i-2]=cosr*d[i-2];
                    slartg(f,g,&cosl,&sinl,&r);
                    d[i-1]=r;
                    f=cosl*e[i-2]+sinl*d[i-2];
                    d[i-2]=cosl*d[i-2]-sinl*e[i-2];
                    if(i>ll+1){ g=sinl*e[i-3]; e[i-3]=cosl*e[i-3]; }
                    wcs[i-ll-1]=cosl; wsn[i-ll-1]=-sinl; wocs[i-ll-1]=cosr; wosn[i-ll-1]=-sinr;
                }
                e[ll-1]=f;
                if(fabsf(e[ll-1])<=thresh) e[ll-1]=0.f;
                if(NC>0)for(int j=m-ll-1;j>=0;j--){
                    float c_=wocs[j],s_=wosn[j]; int r0=ll-1+j;
                    for(int c=0;c<NC;c++){
                        float tmp=VT[(r0+1)*NC+c];
                        VT[(r0+1)*NC+c]=c_*tmp-s_*VT[r0*NC+c];
                        VT[r0*NC+c]=s_*tmp+c_*VT[r0*NC+c];
                    }
                }
                if(NRU>0)for(int j=m-ll-1;j>=0;j--){
                    float c_=wcs[j],s_=wsn[j]; int c0=ll-1+j;
                    for(int r=0;r<NRU;r++){
                        float tmp=U[r*N+c0+1];
                        U[r*N+c0+1]=c_*tmp-s_*U[r*N+c0];
                        U[r*N+c0]=s_*tmp+c_*U[r*N+c0];
                    }
                }
            }
        }
    }
    for(int i=0;i<N;i++){
        if(d[i]<0.f){
            d[i]=-d[i];
            if(NC>0)for(int c=0;c<NC;c++) VT[i*NC+c]=-VT[i*NC+c];
        }
    }
    for(int i=1;i<=N-1;i++){
        int isub=0; float smn=d[0];
        for(int j=1;j<=N-i;j++) if(d[j]<=smn){ isub=j; smn=d[j]; }
        int tg=N-i;
        if(isub!=tg){
            d[isub]=d[tg]; d[tg]=smn;
            if(NC>0)for(int c=0;c<NC;c++){ float t=VT[isub*NC+c]; VT[isub*NC+c]=VT[tg*NC+c]; VT[tg*NC+c]=t; }
            if(NRU>0)for(int r=0;r<NRU;r++){ float t=U[r*N+isub]; U[r*N+isub]=U[r*N+tg]; U[r*N+tg]=t; }
        }
    }
}

// ===========================================================================
// Register-resident bdsqr, N=4, tracking one VT column (y0..y3).
// ===========================================================================
#define DG(i) ((i)==0?d0:((i)==1?d1:((i)==2?d2:d3)))
#define DS(i,v) do{float _t=(v); if((i)==0)d0=_t; else if((i)==1)d1=_t; else if((i)==2)d2=_t; else d3=_t;}while(0)
#define EG(i) ((i)==0?e0:((i)==1?e1:e2))
#define ES(i,v) do{float _t=(v); if((i)==0)e0=_t; else if((i)==1)e1=_t; else e2=_t;}while(0)
#define YG(i) ((i)==0?y0:((i)==1?y1:((i)==2?y2:y3)))
#define YS(i,v) do{float _t=(v); if((i)==0)y0=_t; else if((i)==1)y1=_t; else if((i)==2)y2=_t; else y3=_t;}while(0)
#define YROT(r0,c_,s_) do{ float _c=(c_), _s=(s_);                            \
    if((r0)==0){ float _t=y1; y1=_c*_t-_s*y0; y0=_s*_t+_c*y0; }               \
    else if((r0)==1){ float _t=y2; y2=_c*_t-_s*y1; y1=_s*_t+_c*y1; }          \
    else { float _t=y3; y3=_c*_t-_s*y2; y2=_s*_t+_c*y2; } }while(0)

__device__ __forceinline__ void bdsqr41(float&d0,float&d1,float&d2,float&d3,
                        float&e0,float&e1,float&e2,
                        float&y0,float&y1,float&y2,float&y3){
    const float tol=10.f*LEPS;
    float sminoa=fabsf(d0);
    if(sminoa!=0.f){
        float mu=sminoa; bool z=false;
#pragma unroll
        for(int i=1;i<4;i++){
            if(!z){
                mu=fabsf(DG(i))*fdiv(mu,mu+fabsf(EG(i-1)));
                sminoa=fminf(sminoa,mu);
                if(sminoa==0.f) z=true;
            }
        }
    }
    sminoa*=0.5f;
    float thresh=fmaxf(tol*sminoa,96.0f*LUNFL);
    int m=4, oldll=-1, oldm=-1, idir=0, guard=0;
    float sminl=0.f;
    while(m>1){
        if(++guard>240) break;
        float smax_b=fabsf(DG(m-1));
        int ll=1; bool split=false;
#pragma unroll
        for(int lll=1;lll<=3;lll++){
            if(!split && lll<=m-1){
                int l2=m-lll;
                float abss=fabsf(DG(l2-1)), abse=fabsf(EG(l2-1));
                if(abse<=thresh){ ll=l2; split=true; }
                else smax_b=fmaxf(smax_b,fmaxf(abss,abse));
            }
        }
        if(split){
            ES(ll-1,0.f);
            if(ll==m-1){ m=m-1; continue; }
            ll=ll+1;
        }
        if(ll==m-1){
            float sigmn,sigmx,sinr,cosr,sinl,cosl;
            slasv2(DG(m-2),EG(m-2),DG(m-1),&sigmn,&sigmx,&sinr,&cosr,&sinl,&cosl);
            DS(m-2,sigmx); ES(m-2,0.f); DS(m-1,sigmn);
            YROT(m-2,cosr,sinr);
            m=m-2; continue;
        }
        if(ll>oldm||m<oldll)
            idir=(fabsf(DG(ll-1))>=fabsf(DG(m-1)))?1:2;
        bool cont=false;
        if(idir==1){
            if(fabsf(EG(m-2))<=tol*fabsf(DG(m-1))){ ES(m-2,0.f); cont=true; }
            if(!cont){
                float mu=fabsf(DG(ll-1)); sminl=mu;
#pragma unroll
                for(int lll=1;lll<=3;lll++){
                    if(!cont && lll>=ll && lll<=m-1){
                        if(fabsf(EG(lll-1))<=tol*mu){ ES(lll-1,0.f); cont=true; }
                        else{
                            mu=fabsf(DG(lll))*fdiv(mu,mu+fabsf(EG(lll-1)));
                            sminl=fminf(sminl,mu);
                        }
                    }
                }
            }
        }else{
            if(fabsf(EG(ll-1))<=tol*fabsf(DG(ll-1))){ ES(ll-1,0.f); cont=true; }
            if(!cont){
                float mu=fabsf(DG(m-1)); sminl=mu;
#pragma unroll
                for(int lll=3;lll>=1;lll--){
                    if(!cont && lll>=ll && lll<=m-1){
                        if(fabsf(EG(lll-1))<=tol*mu){ ES(lll-1,0.f); cont=true; }
                        else{
                            mu=fabsf(DG(lll-1))*fdiv(mu,mu+fabsf(EG(lll-1)));
                            sminl=fminf(sminl,mu);
                        }
                    }
                }
            }
        }
        if(cont) continue;
        oldll=ll; oldm=m;
        float shift=0.f, rr;
        if(!(4.0f*tol*fdiv(sminl,smax_b)<=fmaxf(LEPS,0.01f*tol))){
            float sll;
            if(idir==1){ sll=fabsf(DG(ll-1)); slas2(DG(m-2),EG(m-2),DG(m-1),&shift,&rr); }
            else       { sll=fabsf(DG(m-1)); slas2(DG(ll-1),EG(ll-1),DG(ll),&shift,&rr); }
            if(sll>0.f && fdiv(shift,sll)*fdiv(shift,sll)<LEPS) shift=0.f;
        }
        if(shift==0.f){
            if(idir==1){
                float cs=1.f, oldcs=1.f, sn=0.f, oldsn=0.f, r;
#pragma unroll
                for(int i=1;i<=3;i++){
                    if(i>=ll && i<=m-1){
                        slartg(DG(i-1)*cs,EG(i-1),&cs,&sn,&r);
                        if(i>ll) ES(i-2,oldsn*r);
                        float dn; slartg(oldcs*r,DG(i)*sn,&oldcs,&oldsn,&dn);
                        DS(i-1,dn);
                        YROT(i-1,cs,sn);
                    }
                }
                float h=DG(m-1)*cs;
                DS(m-1,h*oldcs); ES(m-2,h*oldsn);
                if(fabsf(EG(m-2))<=thresh) ES(m-2,0.f);
            }else{
                float cs=1.f, oldcs=1.f, sn=0.f, oldsn=0.f, r;
#pragma unroll
                for(int i=4;i>=2;i--){
                    if(i<=m && i>=ll+1){
                        slartg(DG(i-1)*cs,EG(i-2),&cs,&sn,&r);
                        if(i<m) ES(i-1,oldsn*r);
                        float dn; slartg(oldcs*r,DG(i-2)*sn,&oldcs,&oldsn,&dn);
                        DS(i-1,dn);
                        YROT(i-2,oldcs,-oldsn);
                    }
                }
                float h=DG(ll-1)*cs;
                DS(ll-1,h*oldcs); ES(ll-1,h*oldsn);
                if(fabsf(EG(ll-1))<=thresh) ES(ll-1,0.f);
            }
        }else{
            if(idir==1){
                float f=(fabsf(DG(ll-1))-shift)*(fsign(1.f,DG(ll-1))+fdiv(shift,DG(ll-1)));
                float g=EG(ll-1), cosr,sinr,cosl,sinl,r;
#pragma unroll
                for(int i=1;i<=3;i++){
                    if(i>=ll && i<=m-1){
                        slartg(f,g,&cosr,&sinr,&r);
                        if(i>ll) ES(i-2,r);
                        float di1=DG(i-1), ei1=EG(i-1), di=DG(i);
                        f=cosr*di1+sinr*ei1;
                        float ei1n=cosr*ei1-sinr*di1;
                        g=sinr*di;
                        float din=cosr*di;
                        slartg(f,g,&cosl,&sinl,&r);
                        DS(i-1,r);
                        f=cosl*ei1n+sinl*din;
                        DS(i,cosl*din-sinl*ei1n);
                        ES(i-1,ei1n);
                        if(i<m-1){ float ei=EG(i); g=sinl*ei; ES(i,cosl*ei); }
                        YROT(i-1,cosr,sinr);
                    }
                }
                ES(m-2,f);
                if(fabsf(EG(m-2))<=thresh) ES(m-2,0.f);
            }else{
                float f=(fabsf(DG(m-1))-shift)*(fsign(1.f,DG(m-1))+fdiv(shift,DG(m-1)));
                float g=EG(m-2), cosr,sinr,cosl,sinl,r;
#pragma unroll
                for(int i=4;i>=2;i--){
                    if(i<=m && i>=ll+1){
                        slartg(f,g,&cosr,&sinr,&r);
                        if(i<m) ES(i-1,r);
                        float di1=DG(i-1), ei2=EG(i-2), di2=DG(i-2);
                        f=cosr*di1+sinr*ei2;
                        float ei2n=cosr*ei2-sinr*di1;
                        g=sinr*di2;
                        float di2n=cosr*di2;
                        slartg(f,g,&cosl,&sinl,&r);
                        DS(i-1,r);
                        f=cosl*ei2n+sinl*di2n;
                        DS(i-2,cosl*di2n-sinl*ei2n);
                        ES(i-2,ei2n);
                        if(i>ll+1){ float ei3=EG(i-3); g=sinl*ei3; ES(i-3,cosl*ei3); }
                        YROT(i-2,cosr,-sinr);
                    }
                }
                ES(ll-1,f);
                if(fabsf(EG(ll-1))<=thresh) ES(ll-1,0.f);
            }
        }
    }
    if(d0<0.f){ d0=-d0; y0=-y0; }
    if(d1<0.f){ d1=-d1; y1=-y1; }
    if(d2<0.f){ d2=-d2; y2=-y2; }
    if(d3<0.f){ d3=-d3; y3=-y3; }
#pragma unroll
    for(int i=1;i<=3;i++){
        int isub=0; float smn=d0;
#pragma unroll
        for(int j=1;j<=3;j++){
            if(j<=4-i && DG(j)<=smn){ isub=j; smn=DG(j); }
        }
        int tg=4-i;
        if(isub!=tg){
            DS(isub,DG(tg)); DS(tg,smn);
            float t=YG(isub); YS(isub,YG(tg)); YS(tg,t);
        }
    }
}

// one family (+t). Build A, sgebd2 (n=4), track y = P^T e3, bdsqr41.
// __noinline__: single code copy shared by both call sites (I$ footprint).
__device__ __noinline__ void solve_fam(const float* __restrict__ P,
                                       float p1x,float p1y,float p2x,float p2y,
                                       float* z1o, float* wo){
    float A[4][4];
    A[0][0]=-1.f; A[0][1]=0.f;  A[0][2]=p1x; A[0][3]=0.f;
    A[1][0]=0.f;  A[1][1]=-1.f; A[1][2]=p1y; A[1][3]=0.f;
    A[2][0]=p2x*P[8]-P[0]; A[2][1]=p2x*P[9]-P[1];
    A[2][2]=p2x*P[10]-P[2]; A[2][3]=p2x*P[11]-P[3];
    A[3][0]=p2y*P[8]-P[4]; A[3][1]=p2y*P[9]-P[5];
    A[3][2]=p2y*P[10]-P[6]; A[3][3]=p2y*P[11]-P[7];

    float d[4], e[3], tauq[4], taup[3];
#pragma unroll
    for(int i=0;i<4;i++){
        float alpha=A[i][i], xn=0.f;
#pragma unroll
        for(int k=0;k<4;k++) if(k>i) xn+=A[k][i]*A[k][i];
        xn=fsqrt(xn);
        if(xn==0.f){ tauq[i]=0.f; d[i]=alpha; }
        else{
            float beta=-fsign(fsqrt(fmaf(alpha,alpha,xn*xn)),alpha);
            tauq[i]=fdiv(beta-alpha,beta);
            float sc=fdiv(1.f,alpha-beta);
#pragma unroll
            for(int k=0;k<4;k++) if(k>i) A[k][i]*=sc;
            d[i]=beta;
        }
        if(i<3){
#pragma unroll
            for(int j=0;j<4;j++) if(j>i){
                float w=A[i][j];
#pragma unroll
                for(int k=0;k<4;k++) if(k>i) w+=A[k][i]*A[k][j];
                w*=tauq[i];
                A[i][j]-=w;
#pragma unroll
                for(int k=0;k<4;k++) if(k>i) A[k][j]-=w*A[k][i];
            }
            float al2=A[i][i+1], xn2=0.f;
#pragma unroll
            for(int k=0;k<4;k++) if(k>i+1) xn2+=A[i][k]*A[i][k];
            xn2=fsqrt(xn2);
            if(xn2==0.f){ taup[i]=0.f; e[i]=al2; }
            else{
                float beta=-fsign(fsqrt(fmaf(al2,al2,xn2*xn2)),al2);
                taup[i]=fdiv(beta-al2,beta);
                float sc=fdiv(1.f,al2-beta);
#pragma unroll
                for(int k=0;k<4;k++) if(k>i+1) A[i][k]*=sc;
                e[i]=beta;
            }
#pragma unroll
            for(int r=0;r<4;r++) if(r>i){
                float w=A[r][i+1];
#pragma unroll
                for(int k=0;k<4;k++) if(k>i+1) w+=A[i][k]*A[r][k];
                w*=taup[i];
                A[r][i+1]-=w;
#pragma unroll
                for(int k=0;k<4;k++) if(k>i+1) A[r][k]-=w*A[i][k];
            }
        }
    }
    float y0=0.f,y1=0.f,y2=0.f,y3=1.f;
    {   float w=(y1+A[0][2]*y2+A[0][3]*y3)*taup[0];
        y1-=w; y2-=w*A[0][2]; y3-=w*A[0][3]; }
    {   float w=(y2+A[1][3]*y3)*taup[1];
        y2-=w; y3-=w*A[1][3]; }

    float d0=d[0],d1=d[1],d2=d[2],d3=d[3],e0=e[0],e1=e[1],e2=e[2];
    bdsqr41(d0,d1,d2,d3,e0,e1,e2,y0,y1,y2,y3);

    float iy3=fdiv(1.f,y3);
    float pd0=y0*iy3, pd1=y1*iy3, pd2=y2*iy3;
    *z1o=pd2;
    *wo=P[8]*pd0+P[9]*pd1+P[10]*pd2;
}

// ---------------------------------------------------------------------------
// k_setup: 32 blocks x 1 thread — zero intra-warp divergence per batch.
// ---------------------------------------------------------------------------
__global__ void k_setup(const float* __restrict__ Fin, const float* __restrict__ Kin){
    int b=blockIdx.x;
    if(threadIdx.x!=0 || b>=NB) return;
    g_scores[b][0]=0; g_scores[b][1]=0; g_scores[b][2]=0; g_scores[b][3]=0;
    g_counts[b]=0;

    float Km[3][3], Fm[3][3];
#pragma unroll
    for(int r=0;r<3;++r)
#pragma unroll
        for(int c=0;c<3;++c){ Km[r][c]=Kin[b*9+r*3+c]; Fm[r][c]=Fin[b*9+r*3+c]; }
    float T[3][3], A3[3][3];
#pragma unroll
    for(int i=0;i<3;++i)
#pragma unroll
        for(int j=0;j<3;++j){
            float s=0.f;
#pragma unroll
            for(int k=0;k<3;++k) s=fmaf(Km[k][i],Fm[k][j],s);
            T[i][j]=s; }
#pragma unroll
    for(int i=0;i<3;++i)
#pragma unroll
        for(int j=0;j<3;++j){
            float s=0.f;
#pragma unroll
            for(int k=0;k<3;++k) s=fmaf(T[i][k],Km[k][j],s);
            A3[i][j]=s; }

    float d[3], e[2], tauq[3], taup[2];
#pragma unroll
    for(int i=0;i<3;i++){
        float alpha=A3[i][i], xn=0.f;
#pragma unroll
        for(int k=0;k<3;k++) if(k>i) xn+=A3[k][i]*A3[k][i];
        xn=fsqrt(xn);
        if(xn==0.f){ tauq[i]=0.f; d[i]=alpha; }
        else{
            float beta=-fsign(fsqrt(fmaf(alpha,alpha,xn*xn)),alpha);
            tauq[i]=fdiv(beta-alpha,beta);
            float sc=fdiv(1.f,alpha-beta);
#pragma unroll
            for(int k=0;k<3;k++) if(k>i) A3[k][i]*=sc;
            d[i]=beta;
        }
        if(i<2){
#pragma unroll
            for(int j=0;j<3;j++) if(j>i){
                float w=A3[i][j];
#pragma unroll
                for(int k=0;k<3;k++) if(k>i) w+=A3[k][i]*A3[k][j];
                w*=tauq[i];
                A3[i][j]-=w;
#pragma unroll
                for(int k=0;k<3;k++) if(k>i) A3[k][j]-=w*A3[k][i];
            }
            float al2=A3[i][i+1], xn2=0.f;
#pragma unroll
            for(int k=0;k<3;k++) if(k>i+1) xn2+=A3[i][k]*A3[i][k];
            xn2=fsqrt(xn2);
            if(xn2==0.f){ taup[i]=0.f; e[i]=al2; }
            else{
                float beta=-fsign(fsqrt(fmaf(al2,al2,xn2*xn2)),al2);
                taup[i]=fdiv(beta-al2,beta);
                float sc=fdiv(1.f,al2-beta);
#pragma unroll
                for(int k=0;k<3;k++) if(k>i+1) A3[i][k]*=sc;
                e[i]=beta;
            }
#pragma unroll
            for(int r=0;r<3;r++) if(r>i){
                float w=A3[r][i+1];
#pragma unroll
                for(int k=0;k<3;k++) if(k>i+1) w+=A3[i][k]*A3[r][k];
                w*=taup[i];
                A3[r][i+1]-=w;
#pragma unroll
                for(int k=0;k<3;k++) if(k>i+1) A3[r][k]-=w*A3[i][k];
            }
        }
    }
    float Ub[9]={1,0,0,0,1,0,0,0,1}, VTb[9]={1,0,0,0,1,0,0,0,1};
    sbdsqr<3,3,3>(d,e,VTb,Ub);
    float U[3][3], VT[3][3];
#pragma unroll
    for(int c=0;c<3;c++){
        float x0=Ub[0*3+c], x1=Ub[1*3+c], x2=Ub[2*3+c];
        float w=(x1+A3[2][1]*x2)*tauq[1];
        x1-=w; x2-=w*A3[2][1];
        w=(x0+A3[1][0]*x1+A3[2][0]*x2)*tauq[0];
        x0-=w; x1-=w*A3[1][0]; x2-=w*A3[2][0];
        U[0][c]=x0; U[1][c]=x1; U[2][c]=x2;
    }
#pragma unroll
    for(int r=0;r<3;r++){
        float w=(VTb[r*3+1]+A3[0][2]*VTb[r*3+2])*taup[0];
        VT[r][0]=VTb[r*3+0]; VT[r][1]=VTb[r*3+1]-w; VT[r][2]=VTb[r*3+2]-w*A3[0][2];
    }
    float dU = U[0][0]*(U[1][1]*U[2][2]-U[1][2]*U[2][1])
             - U[0][1]*(U[1][0]*U[2][2]-U[1][2]*U[2][0])
             + U[0][2]*(U[1][0]*U[2][1]-U[1][1]*U[2][0]);
    float dV = VT[0][0]*(VT[1][1]*VT[2][2]-VT[1][2]*VT[2][1])
             - VT[0][1]*(VT[1][0]*VT[2][2]-VT[1][2]*VT[2][0])
             + VT[0][2]*(VT[1][0]*VT[2][1]-VT[1][1]*VT[2][0]);
    float sU=(dU<0.f)?-1.f:1.f, sV=(dV<0.f)?-1.f:1.f;
#pragma unroll
    for(int r=0;r<3;r++)
#pragma unroll
        for(int c=0;c<3;c++){ U[r][c]*=sU; VT[r][c]*=sV; }

#pragma unroll
    for(int i=0;i<3;i++){
#pragma unroll
        for(int j=0;j<3;j++){
            float r1= U[i][1]*VT[j][0] - U[i][0]*VT[j][1] + U[i][2]*VT[j][2];
            float r2=-U[i][1]*VT[j][0] + U[i][0]*VT[j][1] + U[i][2]*VT[j][2];
            g_P2[b][0][i*4+j]=r1;
            g_P2[b][1][i*4+j]=r2;
        }
        g_P2[b][0][i*4+3]=U[i][2];
        g_P2[b][1][i*4+3]=U[i][2];
    }
    float f=Km[0][0];
    g_Kn[b][0]=1.0f/f;
    g_Kn[b][1]=-(Km[0][2]/f);
    g_Kn[b][2]=-(Km[1][2]/f);
    g_Kn[b][3]=0.f;
}

// ---------------------------------------------------------------------------
__global__ void __launch_bounds__(256) k_points(
        const float* __restrict__ p1s, const float* __restrict__ p2s,
        const int* __restrict__ bidx, int n){
    int i=blockIdx.x*blockDim.x+threadIdx.x;
    bool act=i<n;
    int b=0;
    bool bit0=false,bit1=false,bit2=false,bit3=false;
    if(act){
        b=bidx[i];
        float invf=g_Kn[b][0], k02=g_Kn[b][1], k12=g_Kn[b][2];
        float p1x=fmaf(invf,p1s[2*i+0],k02);
        float p1y=fmaf(invf,p1s[2*i+1],k12);
        float p2x=fmaf(invf,p2s[2*i+0],k02);
        float p2y=fmaf(invf,p2s[2*i+1],k12);
        const float* P0=g_P2[b][0];
        const float* P1=g_P2[b][1];
        float z1a,wa,z1b,wb;
        solve_fam(P0,p1x,p1y,p2x,p2y,&z1a,&wa);
        solve_fam(P1,p1x,p1y,p2x,p2y,&z1b,&wb);
        float t2a=P0[11], t2b=P1[11];
        bit0=(z1a>0.f)&&(wa+t2a>0.f);
        bit1=(z1a>0.f)&&(wa-t2a>0.f);
        bit2=(z1b>0.f)&&(wb+t2b>0.f);
        bit3=(z1b>0.f)&&(wb-t2b>0.f);
    }
    const unsigned full=0xffffffffu;
    int bkey=act?b:-1;
    int bmax=__reduce_max_sync(full,bkey);
    bool uni=__all_sync(full,(!act)||(bkey==bmax));
    if(uni){
        if(bmax>=0){
            unsigned ba=__ballot_sync(full,act);
            unsigned m0=__ballot_sync(full,act&&bit0);
            unsigned m1=__ballot_sync(full,act&&bit1);
            unsigned m2=__ballot_sync(full,act&&bit2);
            unsigned m3=__ballot_sync(full,act&&bit3);
            if((threadIdx.x&31)==0){
                if(m0) atomicAdd(&g_scores[bmax][0],__popc(m0));
                if(m1) atomicAdd(&g_scores[bmax][1],__popc(m1));
                if(m2) atomicAdd(&g_scores[bmax][2],__popc(m2));
                if(m3) atomicAdd(&g_scores[bmax][3],__popc(m3));
                atomicAdd(&g_counts[bmax],__popc(ba));
            }
        }
    }else if(act){
        if(bit0) atomicAdd(&g_scores[b][0],1);
        if(bit1) atomicAdd(&g_scores[b][1],1);
        if(bit2) atomicAdd(&g_scores[b][2],1);
        if(bit3) atomicAdd(&g_scores[b][3],1);
        atomicAdd(&g_counts[b],1);
    }
}

// ---------------------------------------------------------------------------
__global__ void k_final(float* __restrict__ out, int out_size){
    int b=threadIdx.x;
    if(b>=NB) return;
    int s0=g_scores[b][0],s1=g_scores[b][1],s2=g_scores[b][2],s3=g_scores[b][3];
    int best=0, sm=s0;
    if(s1>sm){best=1;sm=s1;}
    if(s2>sm){best=2;sm=s2;}
    if(s3>sm){best=3;sm=s3;}
    int cnt=g_counts[b];
    float has=(cnt>0)?1.f:0.f;
    int fam=best>>1;
    float sgn=(best&1)?-1.f:1.f;
    const float* P=g_P2[b][fam];
#pragma unroll
    for(int r=0;r<3;r++)
#pragma unroll
        for(int c=0;c<3;c++)
            out[b*9+r*3+c]=P[r*4+c]*has;
    if(out_size>=NB*9+NB*3){
#pragma unroll
        for(int r=0;r<3;r++)
            out[NB*9+b*3+r]=sgn*P[r*4+3]*has;
    }
    if(out_size>=NB*9+NB*3+NB)
        out[NB*9+NB*3+b]=(float)((cnt>0)?best:0);
}

extern "C" void kernel_launch(void* const* d_in, const int* in_sizes, int n_in,
                              void* d_out, int out_size){
    const float* Fm  =(const float*)d_in[0];
    const float* Km  =(const float*)d_in[1];
    const float* pts1=(const float*)d_in[2];
    const float* pts2=(const float*)d_in[3];
    const int*   bidx=(const int*)d_in[4];
    int n=in_sizes[4];
    float* out=(float*)d_out;

    k_setup<<<NB,1>>>(Fm,Km);
    k_points<<<(n+255)/256,256>>>(pts1,pts2,bidx,n);
    k_final<<<1,32>>>(out,out_size);
}

// round 16
// speedup vs baseline: 1.3223x; 1.0352x over previous
#include <cuda_runtime.h>
#include <cuda_bf16.h>

#define NB 32
#define LEPS 5.9604645e-8f
#define LUNFL 1.1754944e-38f

__device__ float g_P2[NB][2][12];
__device__ float g_Kn[NB][4];
__device__ int   g_scores[NB][4];
__device__ int   g_counts[NB];

__device__ __forceinline__ float fsign(float a, float b){ return copysignf(a,b); }
__device__ __forceinline__ float fdiv(float a, float b){ return __fdividef(a,b); }
__device__ __forceinline__ float fsqrt(float x){ return (x<=0.f)?0.f:x*rsqrtf(x); }

// division-free slartg: one MUFU.RSQ, outputs independent off rs
__device__ __forceinline__ void slartg(float f,float g,float*cs,float*sn,float*r){
    if(g==0.f){ *cs=1.f; *sn=0.f; *r=f; }
    else if(f==0.f){ *cs=0.f; *sn=fsign(1.f,g); *r=fabsf(g); }
    else{
        float s2=fmaf(f,f,g*g);
        float rs=rsqrtf(s2);
        float d=s2*rs;
        *cs=fabsf(f)*rs;
        *r=fsign(d,f);
        *sn=g*rs*fsign(1.f,f);
    }
}

__device__ void slas2(float f,float g,float h,float*ssmin,float*ssmax){
    float fa=fabsf(f), ga=fabsf(g), ha=fabsf(h);
    float fhmn=fminf(fa,ha), fhmx=fmaxf(fa,ha);
    if(fhmn==0.f){
        *ssmin=0.f;
        if(fhmx==0.f) *ssmax=ga;
        else{ float mn=fminf(fhmx,ga), mx=fmaxf(fhmx,ga);
              float q=fdiv(mn,mx); *ssmax=mx*fsqrt(1.f+q*q); }
    }else if(ga<fhmx){
        float as=1.f+fdiv(fhmn,fhmx), at=fdiv(fhmx-fhmn,fhmx), au=fdiv(ga,fhmx)*fdiv(ga,fhmx);
        float c=fdiv(2.f,fsqrt(as*as+au)+fsqrt(at*at+au));
        *ssmin=fhmn*c; *ssmax=fdiv(fhmx,c);
    }else{
        float au=fdiv(fhmx,ga);
        if(au==0.f){ *ssmin=fdiv(fhmn*fhmx,ga); *ssmax=ga; }
        else{
            float as=1.f+fdiv(fhmn,fhmx), at=fdiv(fhmx-fhmn,fhmx);
            float c=fdiv(1.f,fsqrt(1.f+(as*au)*(as*au))+fsqrt(1.f+(at*au)*(at*au)));
            float sm=(fhmn*c)*au; *ssmin=sm+sm; *ssmax=fdiv(ga,c+c);
        }
    }
}

__device__ void slasv2(float f,float g,float h,float*ssmin,float*ssmax,
                       float*snr,float*csr,float*snl,float*csl){
    float ft=f, fa=fabsf(f), ht=h, ha=fabsf(h);
    int pmax=1;
    bool swap=(ha>fa);
    if(swap){ pmax=3; float t=ft;ft=ht;ht=t; t=fa;fa=ha;ha=t; }
    float gt=g, ga=fabsf(g);
    float clt=0.f,crt=0.f,slt=0.f,srt=0.f;
    if(ga==0.f){ *ssmin=ha; *ssmax=fa; clt=1.f; crt=1.f; slt=0.f; srt=0.f; }
    else{
        bool gasmal=true;
        if(ga>fa){
            pmax=2;
            if(fdiv(fa,ga)<LEPS){
                gasmal=false; *ssmax=ga;
                *ssmin=(ha>1.f)? fdiv(fa,fdiv(ga,ha)) : fdiv(fa,ga)*ha;
                clt=1.f; slt=fdiv(ht,gt); srt=1.f; crt=fdiv(ft,gt);
            }
        }
        if(gasmal){
            float dd=fa-ha;
            float l=(dd==fa)?1.f:fdiv(dd,fa);
            float m=fdiv(gt,ft), t=2.f-l;
            float mm=m*m, tt=t*t;
            float s=fsqrt(tt+mm);
            float r=(l==0.f)?fabsf(m):fsqrt(l*l+mm);
            float a=0.5f*(s+r);
            *ssmin=fdiv(ha,a); *ssmax=fa*a;
            if(mm==0.f){
                t=(l==0.f)? fsign(2.f,ft)*fsign(1.f,gt) : fdiv(gt,fsign(dd,ft))+fdiv(m,t);
            }else t=(fdiv(m,s+t)+fdiv(m,r+l))*(1.f+a);
            l=fsqrt(fmaf(t,t,4.f));
            crt=fdiv(2.f,l); srt=fdiv(t,l);
            clt=fdiv(crt+srt*m,a); slt=fdiv(ht,ft)*fdiv(srt,a);
        }
    }
    if(swap){ *csl=srt; *snl=crt; *csr=slt; *snr=clt; }
    else{ *csl=clt; *snl=slt; *csr=crt; *snr=srt; }
    float ts=0.f;
    if(pmax==1) ts=fsign(1.f,*csr)*fsign(1.f,*csl)*fsign(1.f,f);
    if(pmax==2) ts=fsign(1.f,*snr)*fsign(1.f,*csl)*fsign(1.f,g);
    if(pmax==3) ts=fsign(1.f,*snr)*fsign(1.f,*snl)*fsign(1.f,h);
    *ssmax=fsign(*ssmax,ts);
    *ssmin=fsign(*ssmin,ts*fsign(1.f,f)*fsign(1.f,h));
}

// ===========================================================================
// Generic sbdsqr (k_setup only). VT: N x NC row-major; U: NRU x N row-major.
// ===========================================================================
template<int N,int NC,int NRU>
__device__ void sbdsqr(float* d, float* e, float* VT, float* U){
    const float tol=10.f*LEPS;
    float sminoa=fabsf(d[0]);
    if(sminoa!=0.f){
        float mu=sminoa;
        for(int i=1;i<N;i++){
            mu=fabsf(d[i])*fdiv(mu,mu+fabsf(e[i-1]));
            sminoa=fminf(sminoa,mu);
            if(sminoa==0.f)break;
        }
    }
    sminoa=fdiv(sminoa,fsqrt((float)N));
    float thresh=fmaxf(tol*sminoa,(float)(6*N*N)*LUNFL);
    int m=N, oldll=-1, oldm=-1, idir=0, guard=0;
    float sminl=0.f;
    float wcs[N],wsn[N],wocs[N],wosn[N];
    while(m>1){
        if(++guard>240) break;
        float smax_b=fabsf(d[m-1]);
        int ll=0; bool split=false;
        for(int lll=1;lll<=m-1;lll++){
            ll=m-lll;
            float abss=fabsf(d[ll-1]), abse=fabsf(e[ll-1]);
            if(abse<=thresh){ split=true; break; }
            smax_b=fmaxf(smax_b,fmaxf(abss,abse));
        }
        if(split){
            e[ll-1]=0.f;
            if(ll==m-1){ m=m-1; continue; }
            ll=ll+1;
        }else ll=1;
        if(ll==m-1){
            float sigmn,sigmx,sinr,cosr,sinl,cosl;
            slasv2(d[m-2],e[m-2],d[m-1],&sigmn,&sigmx,&sinr,&cosr,&sinl,&cosl);
            d[m-2]=sigmx; e[m-2]=0.f; d[m-1]=sigmn;
            if(NC>0)for(int c=0;c<NC;c++){
                float x=VT[(m-2)*NC+c],y=VT[(m-1)*NC+c];
                VT[(m-2)*NC+c]=cosr*x+sinr*y; VT[(m-1)*NC+c]=cosr*y-sinr*x;
            }
            if(NRU>0)for(int r=0;r<NRU;r++){
                float x=U[r*N+m-2],y=U[r*N+m-1];
                U[r*N+m-2]=cosl*x+sinl*y; U[r*N+m-1]=cosl*y-sinl*x;
            }
            m=m-2; continue;
        }
        if(ll>oldm||m<oldll)
            idir=(fabsf(d[ll-1])>=fabsf(d[m-1]))?1:2;
        bool cont=false;
        if(idir==1){
            if(fabsf(e[m-2])<=tol*fabsf(d[m-1])){ e[m-2]=0.f; cont=true; }
            if(!cont){
                float mu=fabsf(d[ll-1]); sminl=mu;
                for(int lll=ll;lll<=m-1;lll++){
                    if(fabsf(e[lll-1])<=tol*mu){ e[lll-1]=0.f; cont=true; break; }
                    mu=fabsf(d[lll])*fdiv(mu,mu+fabsf(e[lll-1]));
                    sminl=fminf(sminl,mu);
                }
            }
        }else{
            if(fabsf(e[ll-1])<=tol*fabsf(d[ll-1])){ e[ll-1]=0.f; cont=true; }
            if(!cont){
                float mu=fabsf(d[m-1]); sminl=mu;
                for(int lll=m-1;lll>=ll;lll--){
                    if(fabsf(e[lll-1])<=tol*mu){ e[lll-1]=0.f; cont=true; break; }
                    mu=fabsf(d[lll-1])*fdiv(mu,mu+fabsf(e[lll-1]));
                    sminl=fminf(sminl,mu);
                }
            }
        }
        if(cont) continue;
        oldll=ll; oldm=m;
        float shift=0.f, rr;
        if(!((float)N*tol*fdiv(sminl,smax_b)<=fmaxf(LEPS,0.01f*tol))){
            float sll;
            if(idir==1){ sll=fabsf(d[ll-1]); slas2(d[m-2],e[m-2],d[m-1],&shift,&rr); }
            else       { sll=fabsf(d[m-1]); slas2(d[ll-1],e[ll-1],d[ll],&shift,&rr); }
            if(sll>0.f && fdiv(shift,sll)*fdiv(shift,sll)<LEPS) shift=0.f;
        }
        if(shift==0.f){
            if(idir==1){
                float cs=1.f, oldcs=1.f, sn=0.f, oldsn=0.f, r;
                for(int i=ll;i<=m-1;i++){
                    slartg(d[i-1]*cs,e[i-1],&cs,&sn,&r);
                    if(i>ll) e[i-2]=oldsn*r;
                    slartg(oldcs*r,d[i]*sn,&oldcs,&oldsn,&d[i-1]);
                    wcs[i-ll]=cs; wsn[i-ll]=sn; wocs[i-ll]=oldcs; wosn[i-ll]=oldsn;
                }
                float h=d[m-1]*cs;
                d[m-1]=h*oldcs; e[m-2]=h*oldsn;
                if(NC>0)for(int j=0;j<m-ll;j++){
                    float c_=wcs[j],s_=wsn[j]; int r0=ll-1+j;
                    for(int c=0;c<NC;c++){
                        float tmp=VT[(r0+1)*NC+c];
                        VT[(r0+1)*NC+c]=c_*tmp-s_*VT[r0*NC+c];
                        VT[r0*NC+c]=s_*tmp+c_*VT[r0*NC+c];
                    }
                }
                if(NRU>0)for(int j=0;j<m-ll;j++){
                    float c_=wocs[j],s_=wosn[j]; int c0=ll-1+j;
                    for(int r=0;r<NRU;r++){
                        float tmp=U[r*N+c0+1];
                        U[r*N+c0+1]=c_*tmp-s_*U[r*N+c0];
                        U[r*N+c0]=s_*tmp+c_*U[r*N+c0];
                    }
                }
                if(fabsf(e[m-2])<=thresh) e[m-2]=0.f;
            }else{
                float cs=1.f, oldcs=1.f, sn=0.f, oldsn=0.f, r;
                for(int i=m;i>=ll+1;i--){
                    slartg(d[i-1]*cs,e[i-2],&cs,&sn,&r);
                    if(i<m) e[i-1]=oldsn*r;
                    slartg(oldcs*r,d[i-2]*sn,&oldcs,&oldsn,&d[i-1]);
                    wcs[i-ll-1]=cs; wsn[i-ll-1]=-sn; wocs[i-ll-1]=oldcs; wosn[i-ll-1]=-oldsn;
                }
                float h=d[ll-1]*cs;
                d[ll-1]=h*oldcs; e[ll-1]=h*oldsn;
                if(NC>0)for(int j=m-ll-1;j>=0;j--){
                    float c_=wocs[j],s_=wosn[j]; int r0=ll-1+j;
                    for(int c=0;c<NC;c++){
                        float tmp=VT[(r0+1)*NC+c];
                        VT[(r0+1)*NC+c]=c_*tmp-s_*VT[r0*NC+c];
                        VT[r0*NC+c]=s_*tmp+c_*VT[r0*NC+c];
                    }
                }
                if(NRU>0)for(int j=m-ll-1;j>=0;j--){
                    float c_=wcs[j],s_=wsn[j]; int c0=ll-1+j;
                    for(int r=0;r<NRU;r++){
                        float tmp=U[r*N+c0+1];
                        U[r*N+c0+1]=c_*tmp-s_*U[r*N+c0];
                        U[r*N+c0]=s_*tmp+c_*U[r*N+c0];
                    }
                }
                if(fabsf(e[ll-1])<=thresh) e[ll-1]=0.f;
            }
        }else{
            if(idir==1){
                float f=(fabsf(d[ll-1])-shift)*(fsign(1.f,d[ll-1])+fdiv(shift,d[ll-1]));
                float g=e[ll-1], cosr,sinr,cosl,sinl,r;
                for(int i=ll;i<=m-1;i++){
                    slartg(f,g,&cosr,&sinr,&r);
                    if(i>ll) e[i-2]=r;
                    f=cosr*d[i-1]+sinr*e[i-1];
                    e[i-1]=cosr*e[i-1]-sinr*d[i-1];
                    g=sinr*d[i];
                    d[i]=cosr*d[i];
                    slartg(f,g,&cosl,&sinl,&r);
                    d[i-1]=r;
                    f=cosl*e[i-1]+sinl*d[i];
                    d[i]=cosl*d[i]-sinl*e[i-1];
                    if(i<m-1){ g=sinl*e[i]; e[i]=cosl*e[i]; }
                    wcs[i-ll]=cosr; wsn[i-ll]=sinr; wocs[i-ll]=cosl; wosn[i-ll]=sinl;
                }
                e[m-2]=f;
                if(NC>0)for(int j=0;j<m-ll;j++){
                    float c_=wcs[j],s_=wsn[j]; int r0=ll-1+j;
                    for(int c=0;c<NC;c++){
                        float tmp=VT[(r0+1)*NC+c];
                        VT[(r0+1)*NC+c]=c_*tmp-s_*VT[r0*NC+c];
                        VT[r0*NC+c]=s_*tmp+c_*VT[r0*NC+c];
                    }
                }
                if(NRU>0)for(int j=0;j<m-ll;j++){
                    float c_=wocs[j],s_=wosn[j]; int c0=ll-1+j;
                    for(int r=0;r<NRU;r++){
                        float tmp=U[r*N+c0+1];
                        U[r*N+c0+1]=c_*tmp-s_*U[r*N+c0];
                        U[r*N+c0]=s_*tmp+c_*U[r*N+c0];
                    }
                }
                if(fabsf(e[m-2])<=thresh) e[m-2]=0.f;
            }else{
                float f=(fabsf(d[m-1])-shift)*(fsign(1.f,d[m-1])+fdiv(shift,d[m-1]));
                float g=e[m-2], cosr,sinr,cosl,sinl,r;
                for(int i=m;i>=ll+1;i--){
                    slartg(f,g,&cosr,&sinr,&r);
                    if(i<m) e[i-1]=r;
                    f=cosr*d[i-1]+sinr*e[i-2];
                    e[i-2]=cosr*e[i-2]-sinr*d[i-1];
                    g=sinr*d[i-2];
                    d[i-2]=cosr*d[i-2];
                    slartg(f,g,&cosl,&sinl,&r);
                    d[i-1]=r;
                    f=cosl*e[i-2]+sinl*d[i-2];
                    d[i-2]=cosl*d[i-2]-sinl*e[i-2];
                    if(i>ll+1){ g=sinl*e[i-3]; e[i-3]=cosl*e[i-3]; }
                    wcs[i-ll-1]=cosl; wsn[i-ll-1]=-sinl; wocs[i-ll-1]=cosr; wosn[i-ll-1]=-sinr;
                }
                e[ll-1]=f;
                if(fabsf(e[ll-1])<=thresh) e[ll-1]=0.f;
                if(NC>0)for(int j=m-ll-1;j>=0;j--){
                    float c_=wocs[j],s_=wosn[j]; int r0=ll-1+j;
                    for(int c=0;c<NC;c++){
                        float tmp=VT[(r0+1)*NC+c];
                        VT[(r0+1)*NC+c]=c_*tmp-s_*VT[r0*NC+c];
                        VT[r0*NC+c]=s_*tmp+c_*VT[r0*NC+c];
                    }
                }
                if(NRU>0)for(int j=m-ll-1;j>=0;j--){
                    float c_=wcs[j],s_=wsn[j]; int c0=ll-1+j;
                    for(int r=0;r<NRU;r++){
                        float tmp=U[r*N+c0+1];
                        U[r*N+c0+1]=c_*tmp-s_*U[r*N+c0];
                        U[r*N+c0]=s_*tmp+c_*U[r*N+c0];
                    }
                }
            }
        }
    }
    for(int i=0;i<N;i++){
        if(d[i]<0.f){
            d[i]=-d[i];
            if(NC>0)for(int c=0;c<NC;c++) VT[i*NC+c]=-VT[i*NC+c];
        }
    }
    for(int i=1;i<=N-1;i++){
        int isub=0; float smn=d[0];
        for(int j=1;j<=N-i;j++) if(d[j]<=smn){ isub=j; smn=d[j]; }
        int tg=N-i;
        if(isub!=tg){
            d[isub]=d[tg]; d[tg]=smn;
            if(NC>0)for(int c=0;c<NC;c++){ float t=VT[isub*NC+c]; VT[isub*NC+c]=VT[tg*NC+c]; VT[tg*NC+c]=t; }
            if(NRU>0)for(int r=0;r<NRU;r++){ float t=U[r*N+isub]; U[r*N+isub]=U[r*N+tg]; U[r*N+tg]=t; }
        }
    }
}

// ===========================================================================
// Register-resident bdsqr, N=4, tracking one VT column (y0..y3).
// ===========================================================================
#define DG(i) ((i)==0?d0:((i)==1?d1:((i)==2?d2:d3)))
#define DS(i,v) do{float _t=(v); if((i)==0)d0=_t; else if((i)==1)d1=_t; else if((i)==2)d2=_t; else d3=_t;}while(0)
#define EG(i) ((i)==0?e0:((i)==1?e1:e2))
#define ES(i,v) do{float _t=(v); if((i)==0)e0=_t; else if((i)==1)e1=_t; else e2=_t;}while(0)
#define YG(i) ((i)==0?y0:((i)==1?y1:((i)==2?y2:y3)))
#define YS(i,v) do{float _t=(v); if((i)==0)y0=_t; else if((i)==1)y1=_t; else if((i)==2)y2=_t; else y3=_t;}while(0)
#define YROT(r0,c_,s_) do{ float _c=(c_), _s=(s_);                            \
    if((r0)==0){ float _t=y1; y1=_c*_t-_s*y0; y0=_s*_t+_c*y0; }               \
    else if((r0)==1){ float _t=y2; y2=_c*_t-_s*y1; y1=_s*_t+_c*y1; }          \
    else { float _t=y3; y3=_c*_t-_s*y2; y2=_s*_t+_c*y2; } }while(0)

__device__ __forceinline__ void bdsqr41(float&d0,float&d1,float&d2,float&d3,
                        float&e0,float&e1,float&e2,
                        float&y0,float&y1,float&y2,float&y3){
    const float tol=10.f*LEPS;
    float sminoa=fabsf(d0);
    if(sminoa!=0.f){
        float mu=sminoa; bool z=false;
#pragma unroll
        for(int i=1;i<4;i++){
            if(!z){
                mu=fabsf(DG(i))*fdiv(mu,mu+fabsf(EG(i-1)));
                sminoa=fminf(sminoa,mu);
                if(sminoa==0.f) z=true;
            }
        }
    }
    sminoa*=0.5f;
    float thresh=fmaxf(tol*sminoa,96.0f*LUNFL);
    int m=4, oldll=-1, oldm=-1, idir=0, guard=0;
    float sminl=0.f;
    while(m>1){
        if(++guard>240) break;
        float smax_b=fabsf(DG(m-1));
        int ll=1; bool split=false;
#pragma unroll
        for(int lll=1;lll<=3;lll++){
            if(!split && lll<=m-1){
                int l2=m-lll;
                float abss=fabsf(DG(l2-1)), abse=fabsf(EG(l2-1));
                if(abse<=thresh){ ll=l2; split=true; }
                else smax_b=fmaxf(smax_b,fmaxf(abss,abse));
            }
        }
        if(split){
            ES(ll-1,0.f);
            if(ll==m-1){ m=m-1; continue; }
            ll=ll+1;
        }
        if(ll==m-1){
            float sigmn,sigmx,sinr,cosr,sinl,cosl;
            slasv2(DG(m-2),EG(m-2),DG(m-1),&sigmn,&sigmx,&sinr,&cosr,&sinl,&cosl);
            DS(m-2,sigmx); ES(m-2,0.f); DS(m-1,sigmn);
            YROT(m-2,cosr,sinr);
            m=m-2; continue;
        }
        if(ll>oldm||m<oldll)
            idir=(fabsf(DG(ll-1))>=fabsf(DG(m-1)))?1:2;
        bool cont=false;
        if(idir==1){
            if(fabsf(EG(m-2))<=tol*fabsf(DG(m-1))){ ES(m-2,0.f); cont=true; }
            if(!cont){
                float mu=fabsf(DG(ll-1)); sminl=mu;
#pragma unroll
                for(int lll=1;lll<=3;lll++){
                    if(!cont && lll>=ll && lll<=m-1){
                        if(fabsf(EG(lll-1))<=tol*mu){ ES(lll-1,0.f); cont=true; }
                        else{
                            mu=fabsf(DG(lll))*fdiv(mu,mu+fabsf(EG(lll-1)));
                            sminl=fminf(sminl,mu);
                        }
                    }
                }
            }
        }else{
            if(fabsf(EG(ll-1))<=tol*fabsf(DG(ll-1))){ ES(ll-1,0.f); cont=true; }
            if(!cont){
                float mu=fabsf(DG(m-1)); sminl=mu;
#pragma unroll
                for(int lll=3;lll>=1;lll--){
                    if(!cont && lll>=ll && lll<=m-1){
                        if(fabsf(EG(lll-1))<=tol*mu){ ES(lll-1,0.f); cont=true; }
                        else{
                            mu=fabsf(DG(lll-1))*fdiv(mu,mu+fabsf(EG(lll-1)));
                            sminl=fminf(sminl,mu);
                        }
                    }
                }
            }
        }
        if(cont) continue;
        oldll=ll; oldm=m;
        float shift=0.f, rr;
        if(!(4.0f*tol*fdiv(sminl,smax_b)<=fmaxf(LEPS,0.01f*tol))){
            float sll;
            if(idir==1){ sll=fabsf(DG(ll-1)); slas2(DG(m-2),EG(m-2),DG(m-1),&shift,&rr); }
            else       { sll=fabsf(DG(m-1)); slas2(DG(ll-1),EG(ll-1),DG(ll),&shift,&rr); }
            if(sll>0.f && fdiv(shift,sll)*fdiv(shift,sll)<LEPS) shift=0.f;
        }
        if(shift==0.f){
            if(idir==1){
                float cs=1.f, oldcs=1.f, sn=0.f, oldsn=0.f, r;
#pragma unroll
                for(int i=1;i<=3;i++){
                    if(i>=ll && i<=m-1){
                        slartg(DG(i-1)*cs,EG(i-1),&cs,&sn,&r);
                        if(i>ll) ES(i-2,oldsn*r);
                        float dn; slartg(oldcs*r,DG(i)*sn,&oldcs,&oldsn,&dn);
                        DS(i-1,dn);
                        YROT(i-1,cs,sn);
                    }
                }
                float h=DG(m-1)*cs;
                DS(m-1,h*oldcs); ES(m-2,h*oldsn);
                if(fabsf(EG(m-2))<=thresh) ES(m-2,0.f);
            }else{
                float cs=1.f, oldcs=1.f, sn=0.f, oldsn=0.f, r;
#pragma unroll
                for(int i=4;i>=2;i--){
                    if(i<=m && i>=ll+1){
                        slartg(DG(i-1)*cs,EG(i-2),&cs,&sn,&r);
                        if(i<m) ES(i-1,oldsn*r);
                        float dn; slartg(oldcs*r,DG(i-2)*sn,&oldcs,&oldsn,&dn);
                        DS(i-1,dn);
                        YROT(i-2,oldcs,-oldsn);
                    }
                }
                float h=DG(ll-1)*cs;
                DS(ll-1,h*oldcs); ES(ll-1,h*oldsn);
                if(fabsf(EG(ll-1))<=thresh) ES(ll-1,0.f);
            }
        }else{
            if(idir==1){
                float f=(fabsf(DG(ll-1))-shift)*(fsign(1.f,DG(ll-1))+fdiv(shift,DG(ll-1)));
                float g=EG(ll-1), cosr,sinr,cosl,sinl,r;
#pragma unroll
                for(int i=1;i<=3;i++){
                    if(i>=ll && i<=m-1){
                        slartg(f,g,&cosr,&sinr,&r);
                        if(i>ll) ES(i-2,r);
                        float di1=DG(i-1), ei1=EG(i-1), di=DG(i);
                        f=cosr*di1+sinr*ei1;
                        float ei1n=cosr*ei1-sinr*di1;
                        g=sinr*di;
                        float din=cosr*di;
                        slartg(f,g,&cosl,&sinl,&r);
                        DS(i-1,r);
                        f=cosl*ei1n+sinl*din;
                        DS(i,cosl*din-sinl*ei1n);
                        ES(i-1,ei1n);
                        if(i<m-1){ float ei=EG(i); g=sinl*ei; ES(i,cosl*ei); }
                        YROT(i-1,cosr,sinr);
                    }
                }
                ES(m-2,f);
                if(fabsf(EG(m-2))<=thresh) ES(m-2,0.f);
            }else{
                float f=(fabsf(DG(m-1))-shift)*(fsign(1.f,DG(m-1))+fdiv(shift,DG(m-1)));
                float g=EG(m-2), cosr,sinr,cosl,sinl,r;
#pragma unroll
                for(int i=4;i>=2;i--){
                    if(i<=m && i>=ll+1){
                        slartg(f,g,&cosr,&sinr,&r);
                        if(i<m) ES(i-1,r);
                        float di1=DG(i-1), ei2=EG(i-2), di2=DG(i-2);
                        f=cosr*di1+sinr*ei2;
                        float ei2n=cosr*ei2-sinr*di1;
                        g=sinr*di2;
                        float di2n=cosr*di2;
                        slartg(f,g,&cosl,&sinl,&r);
                        DS(i-1,r);
                        f=cosl*ei2n+sinl*di2n;
                        DS(i-2,cosl*di2n-sinl*ei2n);
                        ES(i-2,ei2n);
                        if(i>ll+1){ float ei3=EG(i-3); g=sinl*ei3; ES(i-3,cosl*ei3); }
                        YROT(i-2,cosr,-sinr);
                    }
                }
                ES(ll-1,f);
                if(fabsf(EG(ll-1))<=thresh) ES(ll-1,0.f);
            }
        }
    }
    if(d0<0.f){ d0=-d0; y0=-y0; }
    if(d1<0.f){ d1=-d1; y1=-y1; }
    if(d2<0.f){ d2=-d2; y2=-y2; }
    if(d3<0.f){ d3=-d3; y3=-y3; }
#pragma unroll
    for(int i=1;i<=3;i++){
        int isub=0; float smn=d0;
#pragma unroll
        for(int j=1;j<=3;j++){
            if(j<=4-i && DG(j)<=smn){ isub=j; smn=DG(j); }
        }
        int tg=4-i;
        if(isub!=tg){
            DS(isub,DG(tg)); DS(tg,smn);
            float t=YG(isub); YS(isub,YG(tg)); YS(tg,t);
        }
    }
}

// Single shared noinline copy of the QR iteration. s[0..3]=d, s[4..6]=e,
// s[7..10]=y. Only y is written back (epilogue needs nothing else).
__device__ __noinline__ void bdsqr41_mem(float* s){
    float d0=s[0],d1=s[1],d2=s[2],d3=s[3];
    float e0=s[4],e1=s[5],e2=s[6];
    float y0=s[7],y1=s[8],y2=s[9],y3=s[10];
    bdsqr41(d0,d1,d2,d3,e0,e1,e2,y0,y1,y2,y3);
    s[7]=y0; s[8]=y1; s[9]=y2; s[10]=y3;
}

// gebd2 (n=4) for one family: builds A, bidiagonalizes, tracks y = P^T e3.
// Straight-line; inlined twice adjacently so ptxas can interleave the two
// independent dependence chains.
__device__ __forceinline__ void gebd2_4(const float* __restrict__ P,
                                        float p1x,float p1y,float p2x,float p2y,
                                        float* s){
    float A[4][4];
    A[0][0]=-1.f; A[0][1]=0.f;  A[0][2]=p1x; A[0][3]=0.f;
    A[1][0]=0.f;  A[1][1]=-1.f; A[1][2]=p1y; A[1][3]=0.f;
    A[2][0]=p2x*P[8]-P[0]; A[2][1]=p2x*P[9]-P[1];
    A[2][2]=p2x*P[10]-P[2]; A[2][3]=p2x*P[11]-P[3];
    A[3][0]=p2y*P[8]-P[4]; A[3][1]=p2y*P[9]-P[5];
    A[3][2]=p2y*P[10]-P[6]; A[3][3]=p2y*P[11]-P[7];

    float d[4], e[3], tauq[4], taup[3];
#pragma unroll
    for(int i=0;i<4;i++){
        float alpha=A[i][i], xn=0.f;
#pragma unroll
        for(int k=0;k<4;k++) if(k>i) xn+=A[k][i]*A[k][i];
        xn=fsqrt(xn);
        if(xn==0.f){ tauq[i]=0.f; d[i]=alpha; }
        else{
            float beta=-fsign(fsqrt(fmaf(alpha,alpha,xn*xn)),alpha);
            tauq[i]=fdiv(beta-alpha,beta);
            float sc=fdiv(1.f,alpha-beta);
#pragma unroll
            for(int k=0;k<4;k++) if(k>i) A[k][i]*=sc;
            d[i]=beta;
        }
        if(i<3){
#pragma unroll
            for(int j=0;j<4;j++) if(j>i){
                float w=A[i][j];
#pragma unroll
                for(int k=0;k<4;k++) if(k>i) w+=A[k][i]*A[k][j];
                w*=tauq[i];
                A[i][j]-=w;
#pragma unroll
                for(int k=0;k<4;k++) if(k>i) A[k][j]-=w*A[k][i];
            }
            float al2=A[i][i+1], xn2=0.f;
#pragma unroll
            for(int k=0;k<4;k++) if(k>i+1) xn2+=A[i][k]*A[i][k];
            xn2=fsqrt(xn2);
            if(xn2==0.f){ taup[i]=0.f; e[i]=al2; }
            else{
                float beta=-fsign(fsqrt(fmaf(al2,al2,xn2*xn2)),al2);
                taup[i]=fdiv(beta-al2,beta);
                float sc=fdiv(1.f,al2-beta);
#pragma unroll
                for(int k=0;k<4;k++) if(k>i+1) A[i][k]*=sc;
                e[i]=beta;
            }
#pragma unroll
            for(int r=0;r<4;r++) if(r>i){
                float w=A[r][i+1];
#pragma unroll
                for(int k=0;k<4;k++) if(k>i+1) w+=A[i][k]*A[r][k];
                w*=taup[i];
                A[r][i+1]-=w;
#pragma unroll
                for(int k=0;k<4;k++) if(k>i+1) A[r][k]-=w*A[i][k];
            }
        }
    }
    float y0=0.f,y1=0.f,y2=0.f,y3=1.f;
    {   float w=(y1+A[0][2]*y2+A[0][3]*y3)*taup[0];
        y1-=w; y2-=w*A[0][2]; y3-=w*A[0][3]; }
    {   float w=(y2+A[1][3]*y3)*taup[1];
        y2-=w; y3-=w*A[1][3]; }
    s[0]=d[0]; s[1]=d[1]; s[2]=d[2]; s[3]=d[3];
    s[4]=e[0]; s[5]=e[1]; s[6]=e[2];
    s[7]=y0; s[8]=y1; s[9]=y2; s[10]=y3;
}

// ---------------------------------------------------------------------------
// k_setup: 32 blocks x 1 thread — zero intra-warp divergence per batch.
// ---------------------------------------------------------------------------
__global__ void k_setup(const float* __restrict__ Fin, const float* __restrict__ Kin){
    int b=blockIdx.x;
    if(threadIdx.x!=0 || b>=NB) return;
    g_scores[b][0]=0; g_scores[b][1]=0; g_scores[b][2]=0; g_scores[b][3]=0;
    g_counts[b]=0;

    float Km[3][3], Fm[3][3];
#pragma unroll
    for(int r=0;r<3;++r)
#pragma unroll
        for(int c=0;c<3;++c){ Km[r][c]=Kin[b*9+r*3+c]; Fm[r][c]=Fin[b*9+r*3+c]; }
    float T[3][3], A3[3][3];
#pragma unroll
    for(int i=0;i<3;++i)
#pragma unroll
        for(int j=0;j<3;++j){
            float s=0.f;
#pragma unroll
            for(int k=0;k<3;++k) s=fmaf(Km[k][i],Fm[k][j],s);
            T[i][j]=s; }
#pragma unroll
    for(int i=0;i<3;++i)
#pragma unroll
        for(int j=0;j<3;++j){
            float s=0.f;
#pragma unroll
            for(int k=0;k<3;++k) s=fmaf(T[i][k],Km[k][j],s);
            A3[i][j]=s; }

    float d[3], e[2], tauq[3], taup[2];
#pragma unroll
    for(int i=0;i<3;i++){
        float alpha=A3[i][i], xn=0.f;
#pragma unroll
        for(int k=0;k<3;k++) if(k>i) xn+=A3[k][i]*A3[k][i];
        xn=fsqrt(xn);
        if(xn==0.f){ tauq[i]=0.f; d[i]=alpha; }
        else{
            float beta=-fsign(fsqrt(fmaf(alpha,alpha,xn*xn)),alpha);
            tauq[i]=fdiv(beta-alpha,beta);
            float sc=fdiv(1.f,alpha-beta);
#pragma unroll
            for(int k=0;k<3;k++) if(k>i) A3[k][i]*=sc;
            d[i]=beta;
        }
        if(i<2){
#pragma unroll
            for(int j=0;j<3;j++) if(j>i){
                float w=A3[i][j];
#pragma unroll
                for(int k=0;k<3;k++) if(k>i) w+=A3[k][i]*A3[k][j];
                w*=tauq[i];
                A3[i][j]-=w;
#pragma unroll
                for(int k=0;k<3;k++) if(k>i) A3[k][j]-=w*A3[k][i];
            }
            float al2=A3[i][i+1], xn2=0.f;
#pragma unroll
            for(int k=0;k<3;k++) if(k>i+1) xn2+=A3[i][k]*A3[i][k];
            xn2=fsqrt(xn2);
            if(xn2==0.f){ taup[i]=0.f; e[i]=al2; }
            else{
                float beta=-fsign(fsqrt(fmaf(al2,al2,xn2*xn2)),al2);
                taup[i]=fdiv(beta-al2,beta);
                float sc=fdiv(1.f,al2-beta);
#pragma unroll
                for(int k=0;k<3;k++) if(k>i+1) A3[i][k]*=sc;
                e[i]=beta;
            }
#pragma unroll
            for(int r=0;r<3;r++) if(r>i){
                float w=A3[r][i+1];
#pragma unroll
                for(int k=0;k<3;k++) if(k>i+1) w+=A3[i][k]*A3[r][k];
                w*=taup[i];
                A3[r][i+1]-=w;
#pragma unroll
                for(int k=0;k<3;k++) if(k>i+1) A3[r][k]-=w*A3[i][k];
            }
        }
    }
    float Ub[9]={1,0,0,0,1,0,0,0,1}, VTb[9]={1,0,0,0,1,0,0,0,1};
    sbdsqr<3,3,3>(d,e,VTb,Ub);
    float U[3][3], VT[3][3];
#pragma unroll
    for(int c=0;c<3;c++){
        float x0=Ub[0*3+c], x1=Ub[1*3+c], x2=Ub[2*3+c];
        float w=(x1+A3[2][1]*x2)*tauq[1];
        x1-=w; x2-=w*A3[2][1];
        w=(x0+A3[1][0]*x1+A3[2][0]*x2)*tauq[0];
        x0-=w; x1-=w*A3[1][0]; x2-=w*A3[2][0];
        U[0][c]=x0; U[1][c]=x1; U[2][c]=x2;
    }
#pragma unroll
    for(int r=0;r<3;r++){
        float w=(VTb[r*3+1]+A3[0][2]*VTb[r*3+2])*taup[0];
        VT[r][0]=VTb[r*3+0]; VT[r][1]=VTb[r*3+1]-w; VT[r][2]=VTb[r*3+2]-w*A3[0][2];
    }
    float dU = U[0][0]*(U[1][1]*U[2][2]-U[1][2]*U[2][1])
             - U[0][1]*(U[1][0]*U[2][2]-U[1][2]*U[2][0])
             + U[0][2]*(U[1][0]*U[2][1]-U[1][1]*U[2][0]);
    float dV = VT[0][0]*(VT[1][1]*VT[2][2]-VT[1][2]*VT[2][1])
             - VT[0][1]*(VT[1][0]*VT[2][2]-VT[1][2]*VT[2][0])
             + VT[0][2]*(VT[1][0]*VT[2][1]-VT[1][1]*VT[2][0]);
    float sU=(dU<0.f)?-1.f:1.f, sV=(dV<0.f)?-1.f:1.f;
#pragma unroll
    for(int r=0;r<3;r++)
#pragma unroll
        for(int c=0;c<3;c++){ U[r][c]*=sU; VT[r][c]*=sV; }

#pragma unroll
    for(int i=0;i<3;i++){
#pragma unroll
        for(int j=0;j<3;j++){
            float r1= U[i][1]*VT[j][0] - U[i][0]*VT[j][1] + U[i][2]*VT[j][2];
            float r2=-U[i][1]*VT[j][0] + U[i][0]*VT[j][1] + U[i][2]*VT[j][2];
            g_P2[b][0][i*4+j]=r1;
            g_P2[b][1][i*4+j]=r2;
        }
        g_P2[b][0][i*4+3]=U[i][2];
        g_P2[b][1][i*4+3]=U[i][2];
    }
    float f=Km[0][0];
    g_Kn[b][0]=1.0f/f;
    g_Kn[b][1]=-(Km[0][2]/f);
    g_Kn[b][2]=-(Km[1][2]/f);
    g_Kn[b][3]=0.f;
}

// ---------------------------------------------------------------------------
__global__ void __launch_bounds__(256) k_points(
        const float* __restrict__ p1s, const float* __restrict__ p2s,
        const int* __restrict__ bidx, int n){
    int i=blockIdx.x*blockDim.x+threadIdx.x;
    bool act=i<n;
    int b=0;
    bool bit0=false,bit1=false,bit2=false,bit3=false;
    if(act){
        b=bidx[i];
        float invf=g_Kn[b][0], k02=g_Kn[b][1], k12=g_Kn[b][2];
        float2 q1=((const float2*)p1s)[i];
        float2 q2=((const float2*)p2s)[i];
        float p1x=fmaf(invf,q1.x,k02);
        float p1y=fmaf(invf,q1.y,k12);
        float p2x=fmaf(invf,q2.x,k02);
        float p2y=fmaf(invf,q2.y,k12);
        const float* P0=g_P2[b][0];
        const float* P1=g_P2[b][1];
        // two straight-line bidiagonalizations back-to-back (ILP interleave),
        // then the shared noinline QR iteration twice.
        float s0[11], s1[11];
        gebd2_4(P0,p1x,p1y,p2x,p2y,s0);
        gebd2_4(P1,p1x,p1y,p2x,p2y,s1);
        bdsqr41_mem(s0);
        bdsqr41_mem(s1);
        float iy3a=fdiv(1.f,s0[10]);
        float pd0a=s0[7]*iy3a, pd1a=s0[8]*iy3a, pd2a=s0[9]*iy3a;
        float z1a=pd2a;
        float wa=P0[8]*pd0a+P0[9]*pd1a+P0[10]*pd2a;
        float iy3b=fdiv(1.f,s1[10]);
        float pd0b=s1[7]*iy3b, pd1b=s1[8]*iy3b, pd2b=s1[9]*iy3b;
        float z1b=pd2b;
        float wb=P1[8]*pd0b+P1[9]*pd1b+P1[10]*pd2b;
        float t2a=P0[11], t2b=P1[11];
        bit0=(z1a>0.f)&&(wa+t2a>0.f);
        bit1=(z1a>0.f)&&(wa-t2a>0.f);
        bit2=(z1b>0.f)&&(wb+t2b>0.f);
        bit3=(z1b>0.f)&&(wb-t2b>0.f);
    }
    const unsigned full=0xffffffffu;
    int bkey=act?b:-1;
    int bmax=__reduce_max_sync(full,bkey);
    bool uni=__all_sync(full,(!act)||(bkey==bmax));
    if(uni){
        if(bmax>=0){
            unsigned ba=__ballot_sync(full,act);
            unsigned m0=__ballot_sync(full,act&&bit0);
            unsigned m1=__ballot_sync(full,act&&bit1);
            unsigned m2=__ballot_sync(full,act&&bit2);
            unsigned m3=__ballot_sync(full,act&&bit3);
            if((threadIdx.x&31)==0){
                if(m0) atomicAdd(&g_scores[bmax][0],__popc(m0));
                if(m1) atomicAdd(&g_scores[bmax][1],__popc(m1));
                if(m2) atomicAdd(&g_scores[bmax][2],__popc(m2));
                if(m3) atomicAdd(&g_scores[bmax][3],__popc(m3));
                atomicAdd(&g_counts[bmax],__popc(ba));
            }
        }
    }else if(act){
        if(bit0) atomicAdd(&g_scores[b][0],1);
        if(bit1) atomicAdd(&g_scores[b][1],1);
        if(bit2) atomicAdd(&g_scores[b][2],1);
        if(bit3) atomicAdd(&g_scores[b][3],1);
        atomicAdd(&g_counts[b],1);
    }
}

// ---------------------------------------------------------------------------
__global__ void k_final(float* __restrict__ out, int out_size){
    int b=threadIdx.x;
    if(b>=NB) return;
    int s0=g_scores[b][0],s1=g_scores[b][1],s2=g_scores[b][2],s3=g_scores[b][3];
    int best=0, sm=s0;
    if(s1>sm){best=1;sm=s1;}
    if(s2>sm){best=2;sm=s2;}
    if(s3>sm){best=3;sm=s3;}
    int cnt=g_counts[b];
    float has=(cnt>0)?1.f:0.f;
    int fam=best>>1;
    float sgn=(best&1)?-1.f:1.f;
    const float* P=g_P2[b][fam];
#pragma unroll
    for(int r=0;r<3;r++)
#pragma unroll
        for(int c=0;c<3;c++)
            out[b*9+r*3+c]=P[r*4+c]*has;
    if(out_size>=NB*9+NB*3){
#pragma unroll
        for(int r=0;r<3;r++)
            out[NB*9+b*3+r]=sgn*P[r*4+3]*has;
    }
    if(out_size>=NB*9+NB*3+NB)
        out[NB*9+NB*3+b]=(float)((cnt>0)?best:0);
}

extern "C" void kernel_launch(void* const* d_in, const int* in_sizes, int n_in,
                              void* d_out, int out_size){
    const float* Fm  =(const float*)d_in[0];
    const float* Km  =(const float*)d_in[1];
    const float* pts1=(const float*)d_in[2];
    const float* pts2=(const float*)d_in[3];
    const int*   bidx=(const int*)d_in[4];
    int n=in_sizes[4];
    float* out=(float*)d_out;

    k_setup<<<NB,1>>>(Fm,Km);
    k_points<<<(n+255)/256,256>>>(pts1,pts2,bidx,n);
    k_final<<<1,32>>>(out,out_size);
}

// round 17
// speedup vs baseline: 1.4328x; 1.0835x over previous
#include <cuda_runtime.h>
#include <cuda_bf16.h>

#define NB 32
#define LEPS 5.9604645e-8f
#define LUNFL 1.1754944e-38f

__device__ float g_P2[NB][2][12];
__device__ float g_Kn[NB][4];
__device__ int   g_scores[NB][4];
__device__ int   g_counts[NB];

__device__ __forceinline__ float fsign(float a, float b){ return copysignf(a,b); }
__device__ __forceinline__ float fdiv(float a, float b){ return __fdividef(a,b); }
__device__ __forceinline__ float fsqrt(float x){ return (x<=0.f)?0.f:x*rsqrtf(x); }

// division-free slartg: one MUFU.RSQ, outputs independent off rs
__device__ __forceinline__ void slartg(float f,float g,float*cs,float*sn,float*r){
    if(g==0.f){ *cs=1.f; *sn=0.f; *r=f; }
    else if(f==0.f){ *cs=0.f; *sn=fsign(1.f,g); *r=fabsf(g); }
    else{
        float s2=fmaf(f,f,g*g);
        float rs=rsqrtf(s2);
        float d=s2*rs;
        *cs=fabsf(f)*rs;
        *r=fsign(d,f);
        *sn=g*rs*fsign(1.f,f);
    }
}

__device__ void slas2(float f,float g,float h,float*ssmin,float*ssmax){
    float fa=fabsf(f), ga=fabsf(g), ha=fabsf(h);
    float fhmn=fminf(fa,ha), fhmx=fmaxf(fa,ha);
    if(fhmn==0.f){
        *ssmin=0.f;
        if(fhmx==0.f) *ssmax=ga;
        else{ float mn=fminf(fhmx,ga), mx=fmaxf(fhmx,ga);
              float q=fdiv(mn,mx); *ssmax=mx*fsqrt(1.f+q*q); }
    }else if(ga<fhmx){
        float as=1.f+fdiv(fhmn,fhmx), at=fdiv(fhmx-fhmn,fhmx), au=fdiv(ga,fhmx)*fdiv(ga,fhmx);
        float c=fdiv(2.f,fsqrt(as*as+au)+fsqrt(at*at+au));
        *ssmin=fhmn*c; *ssmax=fdiv(fhmx,c);
    }else{
        float au=fdiv(fhmx,ga);
        if(au==0.f){ *ssmin=fdiv(fhmn*fhmx,ga); *ssmax=ga; }
        else{
            float as=1.f+fdiv(fhmn,fhmx), at=fdiv(fhmx-fhmn,fhmx);
            float c=fdiv(1.f,fsqrt(1.f+(as*au)*(as*au))+fsqrt(1.f+(at*au)*(at*au)));
            float sm=(fhmn*c)*au; *ssmin=sm+sm; *ssmax=fdiv(ga,c+c);
        }
    }
}

__device__ void slasv2(float f,float g,float h,float*ssmin,float*ssmax,
                       float*snr,float*csr,float*snl,float*csl){
    float ft=f, fa=fabsf(f), ht=h, ha=fabsf(h);
    int pmax=1;
    bool swap=(ha>fa);
    if(swap){ pmax=3; float t=ft;ft=ht;ht=t; t=fa;fa=ha;ha=t; }
    float gt=g, ga=fabsf(g);
    float clt=0.f,crt=0.f,slt=0.f,srt=0.f;
    if(ga==0.f){ *ssmin=ha; *ssmax=fa; clt=1.f; crt=1.f; slt=0.f; srt=0.f; }
    else{
        bool gasmal=true;
        if(ga>fa){
            pmax=2;
            if(fdiv(fa,ga)<LEPS){
                gasmal=false; *ssmax=ga;
                *ssmin=(ha>1.f)? fdiv(fa,fdiv(ga,ha)) : fdiv(fa,ga)*ha;
                clt=1.f; slt=fdiv(ht,gt); srt=1.f; crt=fdiv(ft,gt);
            }
        }
        if(gasmal){
            float dd=fa-ha;
            float l=(dd==fa)?1.f:fdiv(dd,fa);
            float m=fdiv(gt,ft), t=2.f-l;
            float mm=m*m, tt=t*t;
            float s=fsqrt(tt+mm);
            float r=(l==0.f)?fabsf(m):fsqrt(l*l+mm);
            float a=0.5f*(s+r);
            *ssmin=fdiv(ha,a); *ssmax=fa*a;
            if(mm==0.f){
                t=(l==0.f)? fsign(2.f,ft)*fsign(1.f,gt) : fdiv(gt,fsign(dd,ft))+fdiv(m,t);
            }else t=(fdiv(m,s+t)+fdiv(m,r+l))*(1.f+a);
            l=fsqrt(fmaf(t,t,4.f));
            crt=fdiv(2.f,l); srt=fdiv(t,l);
            clt=fdiv(crt+srt*m,a); slt=fdiv(ht,ft)*fdiv(srt,a);
        }
    }
    if(swap){ *csl=srt; *snl=crt; *csr=slt; *snr=clt; }
    else{ *csl=clt; *snl=slt; *csr=crt; *snr=srt; }
    float ts=0.f;
    if(pmax==1) ts=fsign(1.f,*csr)*fsign(1.f,*csl)*fsign(1.f,f);
    if(pmax==2) ts=fsign(1.f,*snr)*fsign(1.f,*csl)*fsign(1.f,g);
    if(pmax==3) ts=fsign(1.f,*snr)*fsign(1.f,*snl)*fsign(1.f,h);
    *ssmax=fsign(*ssmax,ts);
    *ssmin=fsign(*ssmin,ts*fsign(1.f,f)*fsign(1.f,h));
}

// ===========================================================================
// Generic sbdsqr (k_setup only). VT: N x NC row-major; U: NRU x N row-major.
// ===========================================================================
template<int N,int NC,int NRU>
__device__ void sbdsqr(float* d, float* e, float* VT, float* U){
    const float tol=10.f*LEPS;
    float sminoa=fabsf(d[0]);
    if(sminoa!=0.f){
        float mu=sminoa;
        for(int i=1;i<N;i++){
            mu=fabsf(d[i])*fdiv(mu,mu+fabsf(e[i-1]));
            sminoa=fminf(sminoa,mu);
            if(sminoa==0.f)break;
        }
    }
    sminoa=fdiv(sminoa,fsqrt((float)N));
    float thresh=fmaxf(tol*sminoa,(float)(6*N*N)*LUNFL);
    int m=N, oldll=-1, oldm=-1, idir=0, guard=0;
    float sminl=0.f;
    float wcs[N],wsn[N],wocs[N],wosn[N];
    while(m>1){
        if(++guard>240) break;
        float smax_b=fabsf(d[m-1]);
        int ll=0; bool split=false;
        for(int lll=1;lll<=m-1;lll++){
            ll=m-lll;
            float abss=fabsf(d[ll-1]), abse=fabsf(e[ll-1]);
            if(abse<=thresh){ split=true; break; }
            smax_b=fmaxf(smax_b,fmaxf(abss,abse));
        }
        if(split){
            e[ll-1]=0.f;
            if(ll==m-1){ m=m-1; continue; }
            ll=ll+1;
        }else ll=1;
        if(ll==m-1){
            float sigmn,sigmx,sinr,cosr,sinl,cosl;
            slasv2(d[m-2],e[m-2],d[m-1],&sigmn,&sigmx,&sinr,&cosr,&sinl,&cosl);
            d[m-2]=sigmx; e[m-2]=0.f; d[m-1]=sigmn;
            if(NC>0)for(int c=0;c<NC;c++){
                float x=VT[(m-2)*NC+c],y=VT[(m-1)*NC+c];
                VT[(m-2)*NC+c]=cosr*x+sinr*y; VT[(m-1)*NC+c]=cosr*y-sinr*x;
            }
            if(NRU>0)for(int r=0;r<NRU;r++){
                float x=U[r*N+m-2],y=U[r*N+m-1];
                U[r*N+m-2]=cosl*x+sinl*y; U[r*N+m-1]=cosl*y-sinl*x;
            }
            m=m-2; continue;
        }
        if(ll>oldm||m<oldll)
            idir=(fabsf(d[ll-1])>=fabsf(d[m-1]))?1:2;
        bool cont=false;
        if(idir==1){
            if(fabsf(e[m-2])<=tol*fabsf(d[m-1])){ e[m-2]=0.f; cont=true; }
            if(!cont){
                float mu=fabsf(d[ll-1]); sminl=mu;
                for(int lll=ll;lll<=m-1;lll++){
                    if(fabsf(e[lll-1])<=tol*mu){ e[lll-1]=0.f; cont=true; break; }
                    mu=fabsf(d[lll])*fdiv(mu,mu+fabsf(e[lll-1]));
                    sminl=fminf(sminl,mu);
                }
            }
        }else{
            if(fabsf(e[ll-1])<=tol*fabsf(d[ll-1])){ e[ll-1]=0.f; cont=true; }
            if(!cont){
                float mu=fabsf(d[m-1]); sminl=mu;
                for(int lll=m-1;lll>=ll;lll--){
                    if(fabsf(e[lll-1])<=tol*mu){ e[lll-1]=0.f; cont=true; break; }
                    mu=fabsf(d[lll-1])*fdiv(mu,mu+fabsf(e[lll-1]));
                    sminl=fminf(sminl,mu);
                }
            }
        }
        if(cont) continue;
        oldll=ll; oldm=m;
        float shift=0.f, rr;
        if(!((float)N*tol*fdiv(sminl,smax_b)<=fmaxf(LEPS,0.01f*tol))){
            float sll;
            if(idir==1){ sll=fabsf(d[ll-1]); slas2(d[m-2],e[m-2],d[m-1],&shift,&rr); }
            else       { sll=fabsf(d[m-1]); slas2(d[ll-1],e[ll-1],d[ll],&shift,&rr); }
            if(sll>0.f && fdiv(shift,sll)*fdiv(shift,sll)<LEPS) shift=0.f;
        }
        if(shift==0.f){
            if(idir==1){
                float cs=1.f, oldcs=1.f, sn=0.f, oldsn=0.f, r;
                for(int i=ll;i<=m-1;i++){
                    slartg(d[i-1]*cs,e[i-1],&cs,&sn,&r);
                    if(i>ll) e[i-2]=oldsn*r;
                    slartg(oldcs*r,d[i]*sn,&oldcs,&oldsn,&d[i-1]);
                    wcs[i-ll]=cs; wsn[i-ll]=sn; wocs[i-ll]=oldcs; wosn[i-ll]=oldsn;
                }
                float h=d[m-1]*cs;
                d[m-1]=h*oldcs; e[m-2]=h*oldsn;
                if(NC>0)for(int j=0;j<m-ll;j++){
                    float c_=wcs[j],s_=wsn[j]; int r0=ll-1+j;
                    for(int c=0;c<NC;c++){
                        float tmp=VT[(r0+1)*NC+c];
                        VT[(r0+1)*NC+c]=c_*tmp-s_*VT[r0*NC+c];
                        VT[r0*NC+c]=s_*tmp+c_*VT[r0*NC+c];
                    }
                }
                if(NRU>0)for(int j=0;j<m-ll;j++){
                    float c_=wocs[j],s_=wosn[j]; int c0=ll-1+j;
                    for(int r=0;r<NRU;r++){
                        float tmp=U[r*N+c0+1];
                        U[r*N+c0+1]=c_*tmp-s_*U[r*N+c0];
                        U[r*N+c0]=s_*tmp+c_*U[r*N+c0];
                    }
                }
                if(fabsf(e[m-2])<=thresh) e[m-2]=0.f;
            }else{
                float cs=1.f, oldcs=1.f, sn=0.f, oldsn=0.f, r;
                for(int i=m;i>=ll+1;i--){
                    slartg(d[i-1]*cs,e[i-2],&cs,&sn,&r);
                    if(i<m) e[i-1]=oldsn*r;
                    slartg(oldcs*r,d[i-2]*sn,&oldcs,&oldsn,&d[i-1]);
                    wcs[i-ll-1]=cs; wsn[i-ll-1]=-sn; wocs[i-ll-1]=oldcs; wosn[i-ll-1]=-oldsn;
                }
                float h=d[ll-1]*cs;
                d[ll-1]=h*oldcs; e[ll-1]=h*oldsn;
                if(NC>0)for(int j=m-ll-1;j>=0;j--){
                    float c_=wocs[j],s_=wosn[j]; int r0=ll-1+j;
                    for(int c=0;c<NC;c++){
                        float tmp=VT[(r0+1)*NC+c];
                        VT[(r0+1)*NC+c]=c_*tmp-s_*VT[r0*NC+c];
                        VT[r0*NC+c]=s_*tmp+c_*VT[r0*NC+c];
                    }
                }
                if(NRU>0)for(int j=m-ll-1;j>=0;j--){
                    float c_=wcs[j],s_=wsn[j]; int c0=ll-1+j;
                    for(int r=0;r<NRU;r++){
                        float tmp=U[r*N+c0+1];
                        U[r*N+c0+1]=c_*tmp-s_*U[r*N+c0];
                        U[r*N+c0]=s_*tmp+c_*U[r*N+c0];
                    }
                }
                if(fabsf(e[ll-1])<=thresh) e[ll-1]=0.f;
            }
        }else{
            if(idir==1){
                float f=(fabsf(d[ll-1])-shift)*(fsign(1.f,d[ll-1])+fdiv(shift,d[ll-1]));
                float g=e[ll-1], cosr,sinr,cosl,sinl,r;
                for(int i=ll;i<=m-1;i++){
                    slartg(f,g,&cosr,&sinr,&r);
                    if(i>ll) e[i-2]=r;
                    f=cosr*d[i-1]+sinr*e[i-1];
                    e[i-1]=cosr*e[i-1]-sinr*d[i-1];
                    g=sinr*d[i];
                    d[i]=cosr*d[i];
                    slartg(f,g,&cosl,&sinl,&r);
                    d[i-1]=r;
                    f=cosl*e[i-1]+sinl*d[i];
                    d[i]=cosl*d[i]-sinl*e[i-1];
                    if(i<m-1){ g=sinl*e[i]; e[i]=cosl*e[i]; }
                    wcs[i-ll]=cosr; wsn[i-ll]=sinr; wocs[i-ll]=cosl; wosn[i-ll]=sinl;
                }
                e[m-2]=f;
                if(NC>0)for(int j=0;j<m-ll;j++){
                    float c_=wcs[j],s_=wsn[j]; int r0=ll-1+j;
                    for(int c=0;c<NC;c++){
                        float tmp=VT[(r0+1)*NC+c];
                        VT[(r0+1)*NC+c]=c_*tmp-s_*VT[r0*NC+c];
                        VT[r0*NC+c]=s_*tmp+c_*VT[r0*NC+c];
                    }
                }
                if(NRU>0)for(int j=0;j<m-ll;j++){
                    float c_=wocs[j],s_=wosn[j]; int c0=ll-1+j;
                    for(int r=0;r<NRU;r++){
                        float tmp=U[r*N+c0+1];
                        U[r*N+c0+1]=c_*tmp-s_*U[r*N+c0];
                        U[r*N+c0]=s_*tmp+c_*U[r*N+c0];
                    }
                }
                if(fabsf(e[m-2])<=thresh) e[m-2]=0.f;
            }else{
                float f=(fabsf(d[m-1])-shift)*(fsign(1.f,d[m-1])+fdiv(shift,d[m-1]));
                float g=e[m-2], cosr,sinr,cosl,sinl,r;
                for(int i=m;i>=ll+1;i--){
                    slartg(f,g,&cosr,&sinr,&r);
                    if(i<m) e[i-1]=r;
                    f=cosr*d[i-1]+sinr*e[i-2];
                    e[i-2]=cosr*e[i-2]-sinr*d[i-1];
                    g=sinr*d[i-2];
                    d[i-2]=cosr*d[i-2];
                    slartg(f,g,&cosl,&sinl,&r);
                    d[i-1]=r;
                    f=cosl*e[i-2]+sinl*d[i-2];
                    d[i-2]=cosl*d[i-2]-sinl*e[i-2];
                    if(i>ll+1){ g=sinl*e[i-3]; e[i-3]=cosl*e[i-3]; }
                    wcs[i-ll-1]=cosl; wsn[i-ll-1]=-sinl; wocs[i-ll-1]=cosr; wosn[i-ll-1]=-sinr;
                }
                e[ll-1]=f;
                if(fabsf(e[ll-1])<=thresh) e[ll-1]=0.f;
                if(NC>0)for(int j=m-ll-1;j>=0;j--){
                    float c_=wocs[j],s_=wosn[j]; int r0=ll-1+j;
                    for(int c=0;c<NC;c++){
                        float tmp=VT[(r0+1)*NC+c];
                        VT[(r0+1)*NC+c]=c_*tmp-s_*VT[r0*NC+c];
                        VT[r0*NC+c]=s_*tmp+c_*VT[r0*NC+c];
                    }
                }
                if(NRU>0)for(int j=m-ll-1;j>=0;j--){
                    float c_=wcs[j],s_=wsn[j]; int c0=ll-1+j;
                    for(int r=0;r<NRU;r++){
                        float tmp=U[r*N+c0+1];
                        U[r*N+c0+1]=c_*tmp-s_*U[r*N+c0];
                        U[r*N+c0]=s_*tmp+c_*U[r*N+c0];
                    }
                }
            }
        }
    }
    for(int i=0;i<N;i++){
        if(d[i]<0.f){
            d[i]=-d[i];
            if(NC>0)for(int c=0;c<NC;c++) VT[i*NC+c]=-VT[i*NC+c];
        }
    }
    for(int i=1;i<=N-1;i++){
        int isub=0; float smn=d[0];
        for(int j=1;j<=N-i;j++) if(d[j]<=smn){ isub=j; smn=d[j]; }
        int tg=N-i;
        if(isub!=tg){
            d[isub]=d[tg]; d[tg]=smn;
            if(NC>0)for(int c=0;c<NC;c++){ float t=VT[isub*NC+c]; VT[isub*NC+c]=VT[tg*NC+c]; VT[tg*NC+c]=t; }
            if(NRU>0)for(int r=0;r<NRU;r++){ float t=U[r*N+isub]; U[r*N+isub]=U[r*N+tg]; U[r*N+tg]=t; }
        }
    }
}

// ===========================================================================
// Register-resident bdsqr, N=4, tracking one VT column (y0..y3).
// ===========================================================================
#define DG(i) ((i)==0?d0:((i)==1?d1:((i)==2?d2:d3)))
#define DS(i,v) do{float _t=(v); if((i)==0)d0=_t; else if((i)==1)d1=_t; else if((i)==2)d2=_t; else d3=_t;}while(0)
#define EG(i) ((i)==0?e0:((i)==1?e1:e2))
#define ES(i,v) do{float _t=(v); if((i)==0)e0=_t; else if((i)==1)e1=_t; else e2=_t;}while(0)
#define YG(i) ((i)==0?y0:((i)==1?y1:((i)==2?y2:y3)))
#define YS(i,v) do{float _t=(v); if((i)==0)y0=_t; else if((i)==1)y1=_t; else if((i)==2)y2=_t; else y3=_t;}while(0)
#define YROT(r0,c_,s_) do{ float _c=(c_), _s=(s_);                            \
    if((r0)==0){ float _t=y1; y1=_c*_t-_s*y0; y0=_s*_t+_c*y0; }               \
    else if((r0)==1){ float _t=y2; y2=_c*_t-_s*y1; y1=_s*_t+_c*y1; }          \
    else { float _t=y3; y3=_c*_t-_s*y2; y2=_s*_t+_c*y2; } }while(0)

__device__ __forceinline__ void bdsqr41(float&d0,float&d1,float&d2,float&d3,
                        float&e0,float&e1,float&e2,
                        float&y0,float&y1,float&y2,float&y3){
    const float tol=10.f*LEPS;
    float sminoa=fabsf(d0);
    if(sminoa!=0.f){
        float mu=sminoa; bool z=false;
#pragma unroll
        for(int i=1;i<4;i++){
            if(!z){
                mu=fabsf(DG(i))*fdiv(mu,mu+fabsf(EG(i-1)));
                sminoa=fminf(sminoa,mu);
                if(sminoa==0.f) z=true;
            }
        }
    }
    sminoa*=0.5f;
    float thresh=fmaxf(tol*sminoa,96.0f*LUNFL);
    int m=4, oldll=-1, oldm=-1, idir=0, guard=0;
    float sminl=0.f;
    while(m>1){
        if(++guard>240) break;
        float smax_b=fabsf(DG(m-1));
        int ll=1; bool split=false;
#pragma unroll
        for(int lll=1;lll<=3;lll++){
            if(!split && lll<=m-1){
                int l2=m-lll;
                float abss=fabsf(DG(l2-1)), abse=fabsf(EG(l2-1));
                if(abse<=thresh){ ll=l2; split=true; }
                else smax_b=fmaxf(smax_b,fmaxf(abss,abse));
            }
        }
        if(split){
            ES(ll-1,0.f);
            if(ll==m-1){ m=m-1; continue; }
            ll=ll+1;
        }
        if(ll==m-1){
            float sigmn,sigmx,sinr,cosr,sinl,cosl;
            slasv2(DG(m-2),EG(m-2),DG(m-1),&sigmn,&sigmx,&sinr,&cosr,&sinl,&cosl);
            DS(m-2,sigmx); ES(m-2,0.f); DS(m-1,sigmn);
            YROT(m-2,cosr,sinr);
            m=m-2; continue;
        }
        if(ll>oldm||m<oldll)
            idir=(fabsf(DG(ll-1))>=fabsf(DG(m-1)))?1:2;
        bool cont=false;
        if(idir==1){
            if(fabsf(EG(m-2))<=tol*fabsf(DG(m-1))){ ES(m-2,0.f); cont=true; }
            if(!cont){
                float mu=fabsf(DG(ll-1)); sminl=mu;
#pragma unroll
                for(int lll=1;lll<=3;lll++){
                    if(!cont && lll>=ll && lll<=m-1){
                        if(fabsf(EG(lll-1))<=tol*mu){ ES(lll-1,0.f); cont=true; }
                        else{
                            mu=fabsf(DG(lll))*fdiv(mu,mu+fabsf(EG(lll-1)));
                            sminl=fminf(sminl,mu);
                        }
                    }
                }
            }
        }else{
            if(fabsf(EG(ll-1))<=tol*fabsf(DG(ll-1))){ ES(ll-1,0.f); cont=true; }
            if(!cont){
                float mu=fabsf(DG(m-1)); sminl=mu;
#pragma unroll
                for(int lll=3;lll>=1;lll--){
                    if(!cont && lll>=ll && lll<=m-1){
                        if(fabsf(EG(lll-1))<=tol*mu){ ES(lll-1,0.f); cont=true; }
                        else{
                            mu=fabsf(DG(lll-1))*fdiv(mu,mu+fabsf(EG(lll-1)));
                            sminl=fminf(sminl,mu);
                        }
                    }
                }
            }
        }
        if(cont) continue;
        oldll=ll; oldm=m;
        float shift=0.f, rr;
        if(!(4.0f*tol*fdiv(sminl,smax_b)<=fmaxf(LEPS,0.01f*tol))){
            float sll;
            if(idir==1){ sll=fabsf(DG(ll-1)); slas2(DG(m-2),EG(m-2),DG(m-1),&shift,&rr); }
            else       { sll=fabsf(DG(m-1)); slas2(DG(ll-1),EG(ll-1),DG(ll),&shift,&rr); }
            if(sll>0.f && fdiv(shift,sll)*fdiv(shift,sll)<LEPS) shift=0.f;
        }
        if(shift==0.f){
            if(idir==1){
                float cs=1.f, oldcs=1.f, sn=0.f, oldsn=0.f, r;
#pragma unroll
                for(int i=1;i<=3;i++){
                    if(i>=ll && i<=m-1){
                        slartg(DG(i-1)*cs,EG(i-1),&cs,&sn,&r);
                        if(i>ll) ES(i-2,oldsn*r);
                        float dn; slartg(oldcs*r,DG(i)*sn,&oldcs,&oldsn,&dn);
                        DS(i-1,dn);
                        YROT(i-1,cs,sn);
                    }
                }
                float h=DG(m-1)*cs;
                DS(m-1,h*oldcs); ES(m-2,h*oldsn);
                if(fabsf(EG(m-2))<=thresh) ES(m-2,0.f);
            }else{
                float cs=1.f, oldcs=1.f, sn=0.f, oldsn=0.f, r;
#pragma unroll
                for(int i=4;i>=2;i--){
                    if(i<=m && i>=ll+1){
                        slartg(DG(i-1)*cs,EG(i-2),&cs,&sn,&r);
                        if(i<m) ES(i-1,oldsn*r);
                        float dn; slartg(oldcs*r,DG(i-2)*sn,&oldcs,&oldsn,&dn);
                        DS(i-1,dn);
                        YROT(i-2,oldcs,-oldsn);
                    }
                }
                float h=DG(ll-1)*cs;
                DS(ll-1,h*oldcs); ES(ll-1,h*oldsn);
                if(fabsf(EG(ll-1))<=thresh) ES(ll-1,0.f);
            }
        }else{
            if(idir==1){
                float f=(fabsf(DG(ll-1))-shift)*(fsign(1.f,DG(ll-1))+fdiv(shift,DG(ll-1)));
                float g=EG(ll-1), cosr,sinr,cosl,sinl,r;
#pragma unroll
                for(int i=1;i<=3;i++){
                    if(i>=ll && i<=m-1){
                        slartg(f,g,&cosr,&sinr,&r);
                        if(i>ll) ES(i-2,r);
                        float di1=DG(i-1), ei1=EG(i-1), di=DG(i);
                        f=cosr*di1+sinr*ei1;
                        float ei1n=cosr*ei1-sinr*di1;
                        g=sinr*di;
                        float din=cosr*di;
                        slartg(f,g,&cosl,&sinl,&r);
                        DS(i-1,r);
                        f=cosl*ei1n+sinl*din;
                        DS(i,cosl*din-sinl*ei1n);
                        ES(i-1,ei1n);
                        if(i<m-1){ float ei=EG(i); g=sinl*ei; ES(i,cosl*ei); }
                        YROT(i-1,cosr,sinr);
                    }
                }
                ES(m-2,f);
                if(fabsf(EG(m-2))<=thresh) ES(m-2,0.f);
            }else{
                float f=(fabsf(DG(m-1))-shift)*(fsign(1.f,DG(m-1))+fdiv(shift,DG(m-1)));
                float g=EG(m-2), cosr,sinr,cosl,sinl,r;
#pragma unroll
                for(int i=4;i>=2;i--){
                    if(i<=m && i>=ll+1){
                        slartg(f,g,&cosr,&sinr,&r);
                        if(i<m) ES(i-1,r);
                        float di1=DG(i-1), ei2=EG(i-2), di2=DG(i-2);
                        f=cosr*di1+sinr*ei2;
                        float ei2n=cosr*ei2-sinr*di1;
                        g=sinr*di2;
                        float di2n=cosr*di2;
                        slartg(f,g,&cosl,&sinl,&r);
                        DS(i-1,r);
                        f=cosl*ei2n+sinl*di2n;
                        DS(i-2,cosl*di2n-sinl*ei2n);
                        ES(i-2,ei2n);
                        if(i>ll+1){ float ei3=EG(i-3); g=sinl*ei3; ES(i-3,cosl*ei3); }
                        YROT(i-2,cosr,-sinr);
                    }
                }
                ES(ll-1,f);
                if(fabsf(EG(ll-1))<=thresh) ES(ll-1,0.f);
            }
        }
    }
    if(d0<0.f){ d0=-d0; y0=-y0; }
    if(d1<0.f){ d1=-d1; y1=-y1; }
    if(d2<0.f){ d2=-d2; y2=-y2; }
    if(d3<0.f){ d3=-d3; y3=-y3; }
#pragma unroll
    for(int i=1;i<=3;i++){
        int isub=0; float smn=d0;
#pragma unroll
        for(int j=1;j<=3;j++){
            if(j<=4-i && DG(j)<=smn){ isub=j; smn=DG(j); }
        }
        int tg=4-i;
        if(isub!=tg){
            DS(isub,DG(tg)); DS(tg,smn);
            float t=YG(isub); YS(isub,YG(tg)); YS(tg,t);
        }
    }
}

// ---------------------------------------------------------------------------
// k_setup: 32 blocks x 1 thread — zero intra-warp divergence per batch.
// ---------------------------------------------------------------------------
__global__ void k_setup(const float* __restrict__ Fin, const float* __restrict__ Kin){
    int b=blockIdx.x;
    if(threadIdx.x!=0 || b>=NB) return;
    g_scores[b][0]=0; g_scores[b][1]=0; g_scores[b][2]=0; g_scores[b][3]=0;
    g_counts[b]=0;

    float Km[3][3], Fm[3][3];
#pragma unroll
    for(int r=0;r<3;++r)
#pragma unroll
        for(int c=0;c<3;++c){ Km[r][c]=Kin[b*9+r*3+c]; Fm[r][c]=Fin[b*9+r*3+c]; }
    float T[3][3], A3[3][3];
#pragma unroll
    for(int i=0;i<3;++i)
#pragma unroll
        for(int j=0;j<3;++j){
            float s=0.f;
#pragma unroll
            for(int k=0;k<3;++k) s=fmaf(Km[k][i],Fm[k][j],s);
            T[i][j]=s; }
#pragma unroll
    for(int i=0;i<3;++i)
#pragma unroll
        for(int j=0;j<3;++j){
            float s=0.f;
#pragma unroll
            for(int k=0;k<3;++k) s=fmaf(T[i][k],Km[k][j],s);
            A3[i][j]=s; }

    float d[3], e[2], tauq[3], taup[2];
#pragma unroll
    for(int i=0;i<3;i++){
        float alpha=A3[i][i], xn=0.f;
#pragma unroll
        for(int k=0;k<3;k++) if(k>i) xn+=A3[k][i]*A3[k][i];
        xn=fsqrt(xn);
        if(xn==0.f){ tauq[i]=0.f; d[i]=alpha; }
        else{
            float beta=-fsign(fsqrt(fmaf(alpha,alpha,xn*xn)),alpha);
            tauq[i]=fdiv(beta-alpha,beta);
            float sc=fdiv(1.f,alpha-beta);
#pragma unroll
            for(int k=0;k<3;k++) if(k>i) A3[k][i]*=sc;
            d[i]=beta;
        }
        if(i<2){
#pragma unroll
            for(int j=0;j<3;j++) if(j>i){
                float w=A3[i][j];
#pragma unroll
                for(int k=0;k<3;k++) if(k>i) w+=A3[k][i]*A3[k][j];
                w*=tauq[i];
                A3[i][j]-=w;
#pragma unroll
                for(int k=0;k<3;k++) if(k>i) A3[k][j]-=w*A3[k][i];
            }
            float al2=A3[i][i+1], xn2=0.f;
#pragma unroll
            for(int k=0;k<3;k++) if(k>i+1) xn2+=A3[i][k]*A3[i][k];
            xn2=fsqrt(xn2);
            if(xn2==0.f){ taup[i]=0.f; e[i]=al2; }
            else{
                float beta=-fsign(fsqrt(fmaf(al2,al2,xn2*xn2)),al2);
                taup[i]=fdiv(beta-al2,beta);
                float sc=fdiv(1.f,al2-beta);
#pragma unroll
                for(int k=0;k<3;k++) if(k>i+1) A3[i][k]*=sc;
                e[i]=beta;
            }
#pragma unroll
            for(int r=0;r<3;r++) if(r>i){
                float w=A3[r][i+1];
#pragma unroll
                for(int k=0;k<3;k++) if(k>i+1) w+=A3[i][k]*A3[r][k];
                w*=taup[i];
                A3[r][i+1]-=w;
#pragma unroll
                for(int k=0;k<3;k++) if(k>i+1) A3[r][k]-=w*A3[i][k];
            }
        }
    }
    float Ub[9]={1,0,0,0,1,0,0,0,1}, VTb[9]={1,0,0,0,1,0,0,0,1};
    sbdsqr<3,3,3>(d,e,VTb,Ub);
    float U[3][3], VT[3][3];
#pragma unroll
    for(int c=0;c<3;c++){
        float x0=Ub[0*3+c], x1=Ub[1*3+c], x2=Ub[2*3+c];
        float w=(x1+A3[2][1]*x2)*tauq[1];
        x1-=w; x2-=w*A3[2][1];
        w=(x0+A3[1][0]*x1+A3[2][0]*x2)*tauq[0];
        x0-=w; x1-=w*A3[1][0]; x2-=w*A3[2][0];
        U[0][c]=x0; U[1][c]=x1; U[2][c]=x2;
    }
#pragma unroll
    for(int r=0;r<3;r++){
        float w=(VTb[r*3+1]+A3[0][2]*VTb[r*3+2])*taup[0];
        VT[r][0]=VTb[r*3+0]; VT[r][1]=VTb[r*3+1]-w; VT[r][2]=VTb[r*3+2]-w*A3[0][2];
    }
    float dU = U[0][0]*(U[1][1]*U[2][2]-U[1][2]*U[2][1])
             - U[0][1]*(U[1][0]*U[2][2]-U[1][2]*U[2][0])
             + U[0][2]*(U[1][0]*U[2][1]-U[1][1]*U[2][0]);
    float dV = VT[0][0]*(VT[1][1]*VT[2][2]-VT[1][2]*VT[2][1])
             - VT[0][1]*(VT[1][0]*VT[2][2]-VT[1][2]*VT[2][0])
             + VT[0][2]*(VT[1][0]*VT[2][1]-VT[1][1]*VT[2][0]);
    float sU=(dU<0.f)?-1.f:1.f, sV=(dV<0.f)?-1.f:1.f;
#pragma unroll
    for(int r=0;r<3;r++)
#pragma unroll
        for(int c=0;c<3;c++){ U[r][c]*=sU; VT[r][c]*=sV; }

#pragma unroll
    for(int i=0;i<3;i++){
#pragma unroll
        for(int j=0;j<3;j++){
            float r1= U[i][1]*VT[j][0] - U[i][0]*VT[j][1] + U[i][2]*VT[j][2];
            float r2=-U[i][1]*VT[j][0] + U[i][0]*VT[j][1] + U[i][2]*VT[j][2];
            g_P2[b][0][i*4+j]=r1;
            g_P2[b][1][i*4+j]=r2;
        }
        g_P2[b][0][i*4+3]=U[i][2];
        g_P2[b][1][i*4+3]=U[i][2];
    }
    float f=Km[0][0];
    g_Kn[b][0]=1.0f/f;
    g_Kn[b][1]=-(Km[0][2]/f);
    g_Kn[b][2]=-(Km[1][2]/f);
    g_Kn[b][3]=0.f;
}

// ---------------------------------------------------------------------------
// k_points: ONE thread per (point, family). j>>1 = point, j&1 = family.
// Pairs (2k,2k+1) share a warp; batch_indices sorted -> warps batch-uniform.
// ---------------------------------------------------------------------------
__global__ void __launch_bounds__(256) k_points(
        const float* __restrict__ p1s, const float* __restrict__ p2s,
        const int* __restrict__ bidx, int n){
    int j=blockIdx.x*blockDim.x+threadIdx.x;
    int i=j>>1;
    int fam=j&1;
    bool act=i<n;
    int b=0;
    bool bp=false,bn=false;
    if(act){
        b=bidx[i];
        float invf=g_Kn[b][0], k02=g_Kn[b][1], k12=g_Kn[b][2];
        float2 q1=((const float2*)p1s)[i];
        float2 q2=((const float2*)p2s)[i];
        float p1x=fmaf(invf,q1.x,k02);
        float p1y=fmaf(invf,q1.y,k12);
        float p2x=fmaf(invf,q2.x,k02);
        float p2y=fmaf(invf,q2.y,k12);
        const float* P=g_P2[b][fam];

        // ---- gebd2 (n=4), straight-line, single inline copy ----
        float A[4][4];
        A[0][0]=-1.f; A[0][1]=0.f;  A[0][2]=p1x; A[0][3]=0.f;
        A[1][0]=0.f;  A[1][1]=-1.f; A[1][2]=p1y; A[1][3]=0.f;
        A[2][0]=p2x*P[8]-P[0]; A[2][1]=p2x*P[9]-P[1];
        A[2][2]=p2x*P[10]-P[2]; A[2][3]=p2x*P[11]-P[3];
        A[3][0]=p2y*P[8]-P[4]; A[3][1]=p2y*P[9]-P[5];
        A[3][2]=p2y*P[10]-P[6]; A[3][3]=p2y*P[11]-P[7];

        float d[4], e[3], tauq[4], taup[3];
#pragma unroll
        for(int ii=0;ii<4;ii++){
            float alpha=A[ii][ii], xn=0.f;
#pragma unroll
            for(int k=0;k<4;k++) if(k>ii) xn+=A[k][ii]*A[k][ii];
            xn=fsqrt(xn);
            if(xn==0.f){ tauq[ii]=0.f; d[ii]=alpha; }
            else{
                float beta=-fsign(fsqrt(fmaf(alpha,alpha,xn*xn)),alpha);
                tauq[ii]=fdiv(beta-alpha,beta);
                float sc=fdiv(1.f,alpha-beta);
#pragma unroll
                for(int k=0;k<4;k++) if(k>ii) A[k][ii]*=sc;
                d[ii]=beta;
            }
            if(ii<3){
#pragma unroll
                for(int jj=0;jj<4;jj++) if(jj>ii){
                    float w=A[ii][jj];
#pragma unroll
                    for(int k=0;k<4;k++) if(k>ii) w+=A[k][ii]*A[k][jj];
                    w*=tauq[ii];
                    A[ii][jj]-=w;
#pragma unroll
                    for(int k=0;k<4;k++) if(k>ii) A[k][jj]-=w*A[k][ii];
                }
                float al2=A[ii][ii+1], xn2=0.f;
#pragma unroll
                for(int k=0;k<4;k++) if(k>ii+1) xn2+=A[ii][k]*A[ii][k];
                xn2=fsqrt(xn2);
                if(xn2==0.f){ taup[ii]=0.f; e[ii]=al2; }
                else{
                    float beta=-fsign(fsqrt(fmaf(al2,al2,xn2*xn2)),al2);
                    taup[ii]=fdiv(beta-al2,beta);
                    float sc=fdiv(1.f,al2-beta);
#pragma unroll
                    for(int k=0;k<4;k++) if(k>ii+1) A[ii][k]*=sc;
                    e[ii]=beta;
                }
#pragma unroll
                for(int r=0;r<4;r++) if(r>ii){
                    float w=A[r][ii+1];
#pragma unroll
                    for(int k=0;k<4;k++) if(k>ii+1) w+=A[ii][k]*A[r][k];
                    w*=taup[ii];
                    A[r][ii+1]-=w;
#pragma unroll
                    for(int k=0;k<4;k++) if(k>ii+1) A[r][k]-=w*A[ii][k];
                }
            }
        }
        float y0=0.f,y1=0.f,y2=0.f,y3=1.f;
        {   float w=(y1+A[0][2]*y2+A[0][3]*y3)*taup[0];
            y1-=w; y2-=w*A[0][2]; y3-=w*A[0][3]; }
        {   float w=(y2+A[1][3]*y3)*taup[1];
            y2-=w; y3-=w*A[1][3]; }

        float d0=d[0],d1=d[1],d2=d[2],d3=d[3],e0=e[0],e1=e[1],e2=e[2];
        bdsqr41(d0,d1,d2,d3,e0,e1,e2,y0,y1,y2,y3);

        float iy3=fdiv(1.f,y3);
        float pd0=y0*iy3, pd1=y1*iy3, pd2=y2*iy3;
        float z1=pd2;
        float w=P[8]*pd0+P[9]*pd1+P[10]*pd2;
        float t2=P[11];
        bp=(z1>0.f)&&(w+t2>0.f);
        bn=(z1>0.f)&&(w-t2>0.f);
    }
    const unsigned full=0xffffffffu;
    int bkey=act?b:-1;
    int bmax=__reduce_max_sync(full,bkey);
    bool uni=__all_sync(full,(!act)||(bkey==bmax));
    if(uni){
        if(bmax>=0){
            unsigned ba=__ballot_sync(full,act&&(fam==0));
            unsigned m0=__ballot_sync(full,act&&(fam==0)&&bp);
            unsigned m1=__ballot_sync(full,act&&(fam==0)&&bn);
            unsigned m2=__ballot_sync(full,act&&(fam==1)&&bp);
            unsigned m3=__ballot_sync(full,act&&(fam==1)&&bn);
            if((threadIdx.x&31)==0){
                if(m0) atomicAdd(&g_scores[bmax][0],__popc(m0));
                if(m1) atomicAdd(&g_scores[bmax][1],__popc(m1));
                if(m2) atomicAdd(&g_scores[bmax][2],__popc(m2));
                if(m3) atomicAdd(&g_scores[bmax][3],__popc(m3));
                atomicAdd(&g_counts[bmax],__popc(ba));
            }
        }
    }else if(act){
        int c0=fam*2, c1=fam*2+1;
        if(bp) atomicAdd(&g_scores[b][c0],1);
        if(bn) atomicAdd(&g_scores[b][c1],1);
        if(fam==0) atomicAdd(&g_counts[b],1);
    }
}

// ---------------------------------------------------------------------------
__global__ void k_final(float* __restrict__ out, int out_size){
    int b=threadIdx.x;
    if(b>=NB) return;
    int s0=g_scores[b][0],s1=g_scores[b][1],s2=g_scores[b][2],s3=g_scores[b][3];
    int best=0, sm=s0;
    if(s1>sm){best=1;sm=s1;}
    if(s2>sm){best=2;sm=s2;}
    if(s3>sm){best=3;sm=s3;}
    int cnt=g_counts[b];
    float has=(cnt>0)?1.f:0.f;
    int fam=best>>1;
    float sgn=(best&1)?-1.f:1.f;
    const float* P=g_P2[b][fam];
#pragma unroll
    for(int r=0;r<3;r++)
#pragma unroll
        for(int c=0;c<3;c++)
            out[b*9+r*3+c]=P[r*4+c]*has;
    if(out_size>=NB*9+NB*3){
#pragma unroll
        for(int r=0;r<3;r++)
            out[NB*9+b*3+r]=sgn*P[r*4+3]*has;
    }
    if(out_size>=NB*9+NB*3+NB)
        out[NB*9+NB*3+b]=(float)((cnt>0)?best:0);
}

extern "C" void kernel_launch(void* const* d_in, const int* in_sizes, int n_in,
                              void* d_out, int out_size){
    const float* Fm  =(const float*)d_in[0];
    const float* Km  =(const float*)d_in[1];
    const float* pts1=(const float*)d_in[2];
    const float* pts2=(const float*)d_in[3];
    const int*   bidx=(const int*)d_in[4];
    int n=in_sizes[4];
    float* out=(float*)d_out;

    k_setup<<<NB,1>>>(Fm,Km);
    int threads2=2*n;
    k_points<<<(threads2+255)/256,256>>>(pts1,pts2,bidx,n);
    k_final<<<1,32>>>(out,out_size);
}